// round 12
// baseline (speedup 1.0000x reference)
#include <cuda_runtime.h>
#include <cuda_bf16.h>
#include <math.h>
#include <stdint.h>

#define N_Q   8192
#define M_KV  8192
#define DIM   256
#define KNB   32
#define TAU_F 0.07f
#define EPS_F 1e-8f

#define KCAT  768    // 3 split-term segments x 256  (hh + hm + mh)

// ---------------- scratch (device globals; allocation-free) ----------------
__device__ float g_F[16384 * 256];                          // 16 MB features pre-norm
__device__ float g_fxn[(size_t)N_Q * DIM];                  // 8 MB fp32 normalized x
__device__ float g_fyn[(size_t)M_KV * DIM];                 // 8 MB fp32 normalized y
__device__ __nv_bfloat16 g_axc[(size_t)N_Q * KCAT];         // 12 MB A concat splits (h,h,m)
__device__ __nv_bfloat16 g_byc[(size_t)M_KV * KCAT];        // 12 MB B concat splits (h,m,h)
__device__ float g_sim[(size_t)N_Q * M_KV];                 // 256 MB approx similarity
__device__ int   g_cand[(size_t)N_Q * 64];                  // 2 MB top-64 candidate ids

typedef unsigned long long u64;
typedef unsigned int u32;

// ---------------- f32x2 helpers (feat GEMM) ----------------
__device__ __forceinline__ u64 pk2(float lo, float hi) {
    u64 r; asm("mov.b64 %0, {%1, %2};" : "=l"(r) : "f"(lo), "f"(hi)); return r;
}
__device__ __forceinline__ void unpk2(u64 p, float& lo, float& hi) {
    asm("mov.b64 {%0, %1}, %2;" : "=f"(lo), "=f"(hi) : "l"(p));
}
__device__ __forceinline__ void ffma2(u64& d, u64 a, u64 b) {
    asm("fma.rn.f32x2 %0, %1, %2, %0;" : "+l"(d) : "l"(a), "l"(b));
}

// ---------------------------------------------------------------------------
// Kernel 1: F = [x;y] @ W^T + b   (fp32 exact; R1 body — best measured)
// ---------------------------------------------------------------------------
#define FBM 128
#define FBN 128
#define FBK 16
#define FSST 132

__global__ __launch_bounds__(256, 2)
void feat_gemm_kernel(const float* __restrict__ x, const float* __restrict__ y,
                      const float* __restrict__ W, const float* __restrict__ bias)
{
    __shared__ float As[FBK * FSST];
    __shared__ float Bs[FBK * FSST];
    const int tid = threadIdx.x;
    const int tr  = tid >> 4;
    const int tc  = tid & 15;
    const int r0  = blockIdx.y * FBM;
    const int c0  = blockIdx.x * FBN;

    u64 acc[8][4];
#pragma unroll
    for (int i = 0; i < 8; i++)
#pragma unroll
        for (int j = 0; j < 4; j++) acc[i][j] = 0ull;

    for (int k0 = 0; k0 < DIM; k0 += FBK) {
#pragma unroll
        for (int ld = 0; ld < 2; ld++) {
            int pos = tid + ld * 256;
            int r   = pos >> 2;
            int kg  = pos & 3;
            int gr  = r0 + r;
            const float* src = (gr < N_Q) ? (x + (size_t)gr * DIM)
                                          : (y + (size_t)(gr - N_Q) * DIM);
            float4 v = *(const float4*)(src + k0 + kg * 4);
            As[(kg * 4 + 0) * FSST + r] = v.x;
            As[(kg * 4 + 1) * FSST + r] = v.y;
            As[(kg * 4 + 2) * FSST + r] = v.z;
            As[(kg * 4 + 3) * FSST + r] = v.w;
        }
#pragma unroll
        for (int ld = 0; ld < 2; ld++) {
            int pos = tid + ld * 256;
            int c   = pos >> 2;
            int kg  = pos & 3;
            float4 v = *(const float4*)(W + (size_t)(c0 + c) * DIM + k0 + kg * 4);
            Bs[(kg * 4 + 0) * FSST + c] = v.x;
            Bs[(kg * 4 + 1) * FSST + c] = v.y;
            Bs[(kg * 4 + 2) * FSST + c] = v.z;
            Bs[(kg * 4 + 3) * FSST + c] = v.w;
        }
        __syncthreads();
#pragma unroll
        for (int kk = 0; kk < FBK; kk++) {
            const float* ar = As + kk * FSST + tr * 8;
            const u64*   br = (const u64*)(Bs + kk * FSST + tc * 8);
            float4 a0 = *(const float4*)(ar);
            float4 a1 = *(const float4*)(ar + 4);
            u64 b0 = br[0], b1 = br[1], b2 = br[2], b3 = br[3];
            float av[8] = {a0.x, a0.y, a0.z, a0.w, a1.x, a1.y, a1.z, a1.w};
#pragma unroll
            for (int i = 0; i < 8; i++) {
                u64 ai = pk2(av[i], av[i]);
                ffma2(acc[i][0], ai, b0);
                ffma2(acc[i][1], ai, b1);
                ffma2(acc[i][2], ai, b2);
                ffma2(acc[i][3], ai, b3);
            }
        }
        __syncthreads();
    }

    float bl[8];
#pragma unroll
    for (int u = 0; u < 8; u++) bl[u] = bias[c0 + tc * 8 + u];
#pragma unroll
    for (int i = 0; i < 8; i++) {
        int row = r0 + tr * 8 + i;
        float* dst = g_F + (size_t)row * DIM + c0 + tc * 8;
        float4 w0, w1;
        unpk2(acc[i][0], w0.x, w0.y); unpk2(acc[i][1], w0.z, w0.w);
        unpk2(acc[i][2], w1.x, w1.y); unpk2(acc[i][3], w1.z, w1.w);
        w0.x += bl[0]; w0.y += bl[1]; w0.z += bl[2]; w0.w += bl[3];
        w1.x += bl[4]; w1.y += bl[5]; w1.z += bl[6]; w1.w += bl[7];
        *(float4*)dst       = w0;
        *(float4*)(dst + 4) = w1;
    }
}

// ---------------------------------------------------------------------------
// Kernel 2: L2-normalize rows of F; store fp32 (for sequential re-rank) and
// the bf16 split concat operands:  A segs (h,h,m)  B segs (h,m,h)
// ---------------------------------------------------------------------------
__global__ __launch_bounds__(256)
void normalize_split_kernel()
{
    const int row = blockIdx.x;
    const int t   = threadIdx.x;
    float v = g_F[(size_t)row * DIM + t];
    float sq = v * v;
#pragma unroll
    for (int o = 16; o > 0; o >>= 1) sq += __shfl_xor_sync(0xffffffffu, sq, o);
    __shared__ float ws[8];
    __shared__ float sres;
    if ((t & 31) == 0) ws[t >> 5] = sq;
    __syncthreads();
    if (t < 32) {
        float total = (t < 8) ? ws[t] : 0.0f;
#pragma unroll
        for (int o = 4; o > 0; o >>= 1) total += __shfl_xor_sync(0xffffffffu, total, o);
        if (t == 0) sres = rsqrtf(total + EPS_F);
    }
    __syncthreads();
    float vn = v * sres;

    __nv_bfloat16 h = __float2bfloat16_rn(vn);
    float r1 = vn - __bfloat162float(h);
    __nv_bfloat16 m = __float2bfloat16_rn(r1);

    if (row < N_Q) {
        g_fxn[(size_t)row * DIM + t] = vn;
        __nv_bfloat16* p = g_axc + (size_t)row * KCAT + t;
        p[0*DIM] = h; p[1*DIM] = h; p[2*DIM] = m;
    } else {
        int r = row - N_Q;
        g_fyn[(size_t)r * DIM + t] = vn;
        __nv_bfloat16* p = g_byc + (size_t)r * KCAT + t;
        p[0*DIM] = h; p[1*DIM] = m; p[2*DIM] = h;
    }
}

// ---------------------------------------------------------------------------
// Kernel 3: sim = A_cat @ B_cat^T  (8192 x 8192 x 768) on HMMA.  (unchanged)
// ---------------------------------------------------------------------------
#define SBM 256
#define SBN 128
#define NSTAGE 3
#define A_STG (SBM * 128)
#define B_STG (SBN * 128)
#define STG   (A_STG + B_STG)
#define SIM_SMEM (NSTAGE * STG)       // 144 KB
#define NKSTAGES (KCAT / 64)          // 12

#define SWZ(o) ((o) ^ (((o) >> 3) & 0x70))

__device__ __forceinline__ u32 s2u(const void* p) {
    u32 a; asm("{ .reg .u64 t; cvta.to.shared.u64 t, %1; cvt.u32.u64 %0, t; }"
               : "=r"(a) : "l"(p)); return a;
}
__device__ __forceinline__ void cp16(u32 dst, const void* src) {
    asm volatile("cp.async.cg.shared.global [%0], [%1], 16;"
                 :: "r"(dst), "l"(src) : "memory");
}
__device__ __forceinline__ void ldsm4(u32* r, u32 addr) {
    asm volatile("ldmatrix.sync.aligned.m8n8.x4.shared.b16 {%0,%1,%2,%3}, [%4];"
                 : "=r"(r[0]), "=r"(r[1]), "=r"(r[2]), "=r"(r[3]) : "r"(addr));
}
__device__ __forceinline__ void mma16816(float* c, const u32* a, const u32* b) {
    asm volatile(
        "mma.sync.aligned.m16n8k16.row.col.f32.bf16.bf16.f32 "
        "{%0,%1,%2,%3}, {%4,%5,%6,%7}, {%8,%9}, {%0,%1,%2,%3};"
        : "+f"(c[0]), "+f"(c[1]), "+f"(c[2]), "+f"(c[3])
        : "r"(a[0]), "r"(a[1]), "r"(a[2]), "r"(a[3]), "r"(b[0]), "r"(b[1]));
}

__global__ __launch_bounds__(256, 1)
void sim_mma_kernel()
{
    extern __shared__ char dyn[];
    const u32 sbase = s2u(dyn);
    const int tid  = threadIdx.x;
    const int wid  = tid >> 5;
    const int lane = tid & 31;
    const int wm   = wid >> 1;
    const int wn   = wid & 1;
    const int r0   = blockIdx.y * SBM;
    const int c0   = blockIdx.x * SBN;

    float acc[4][8][4];
#pragma unroll
    for (int i = 0; i < 4; i++)
#pragma unroll
        for (int j = 0; j < 8; j++)
#pragma unroll
            for (int q = 0; q < 4; q++) acc[i][j][q] = 0.0f;

    auto loadStage = [&](int s) {
        const int buf = s % NSTAGE;
        const u32 sA = sbase + buf * STG;
        const u32 sB = sA + A_STG;
        const __nv_bfloat16* gA = g_axc + (size_t)r0 * KCAT + s * 64;
        const __nv_bfloat16* gB = g_byc + (size_t)c0 * KCAT + s * 64;
#pragma unroll
        for (int i = 0; i < 8; i++) {
            int id = tid + i * 256;
            int r = id >> 3, kc = id & 7;
            cp16(sA + SWZ(r * 128 + kc * 16), gA + (size_t)r * KCAT + kc * 8);
        }
#pragma unroll
        for (int i = 0; i < 4; i++) {
            int id = tid + i * 256;
            int r = id >> 3, kc = id & 7;
            cp16(sB + SWZ(r * 128 + kc * 16), gB + (size_t)r * KCAT + kc * 8);
        }
        asm volatile("cp.async.commit_group;" ::: "memory");
    };

    loadStage(0);
    loadStage(1);

    for (int s = 0; s < NKSTAGES; s++) {
        if (s + 2 < NKSTAGES)
            asm volatile("cp.async.wait_group 1;" ::: "memory");
        else
            asm volatile("cp.async.wait_group 0;" ::: "memory");
        __syncthreads();
        if (s + 2 < NKSTAGES) loadStage(s + 2);

        const int buf = s % NSTAGE;
        const u32 sA = sbase + buf * STG;
        const u32 sB = sA + A_STG;

#pragma unroll
        for (int ks = 0; ks < 4; ks++) {
            u32 afr[4][4], bfr[4][4];
#pragma unroll
            for (int mt = 0; mt < 4; mt++) {
                int mr = wm * 64 + mt * 16 + (lane & 15);
                int kb = ks * 32 + (lane >> 4) * 16;
                ldsm4(afr[mt], sA + SWZ(mr * 128 + kb));
            }
#pragma unroll
            for (int np = 0; np < 4; np++) {
                int nr = wn * 64 + np * 16 + ((lane >> 4) & 1) * 8 + (lane & 7);
                int kb = ks * 32 + ((lane >> 3) & 1) * 16;
                ldsm4(bfr[np], sB + SWZ(nr * 128 + kb));
            }
#pragma unroll
            for (int mt = 0; mt < 4; mt++)
#pragma unroll
                for (int nt = 0; nt < 8; nt++)
                    mma16816(acc[mt][nt], afr[mt], &bfr[nt >> 1][(nt & 1) * 2]);
        }
    }

#pragma unroll
    for (int mt = 0; mt < 4; mt++) {
        int rlo = r0 + wm * 64 + mt * 16 + (lane >> 2);
#pragma unroll
        for (int nt = 0; nt < 8; nt++) {
            int col = c0 + wn * 64 + nt * 8 + (lane & 3) * 2;
            float2 v0 = make_float2(acc[mt][nt][0], acc[mt][nt][1]);
            float2 v1 = make_float2(acc[mt][nt][2], acc[mt][nt][3]);
            *(float2*)(g_sim + (size_t)rlo * M_KV + col)       = v0;
            *(float2*)(g_sim + (size_t)(rlo + 8) * M_KV + col) = v1;
        }
    }
}

// ---------------------------------------------------------------------------
// top-k helpers
// ---------------------------------------------------------------------------
__device__ __forceinline__ u32 ordf(float f) {
    u32 b = __float_as_uint(f);
    return (b & 0x80000000u) ? ~b : (b | 0x80000000u);
}
__device__ __forceinline__ float key_val(u64 k) {
    u32 o = (u32)(k >> 32);
    u32 b = (o & 0x80000000u) ? (o ^ 0x80000000u) : ~o;
    return __uint_as_float(b);
}
__device__ __forceinline__ u64 make_key(float v, int idx) {
    return ((u64)ordf(v) << 32) | (u32)(~(u32)idx);
}
__device__ __forceinline__ u64 kmax(u64 a, u64 b) { return a > b ? a : b; }
__device__ __forceinline__ u64 kmin(u64 a, u64 b) { return a < b ? a : b; }
__device__ __forceinline__ u64 shflx(u64 v, int m) {
    return __shfl_xor_sync(0xffffffffu, v, m);
}
__device__ __forceinline__ void sort32(u64& c, int lane) {
#pragma unroll
    for (int k = 2; k <= 32; k <<= 1) {
#pragma unroll
        for (int j = k >> 1; j > 0; j >>= 1) {
            u64 o = shflx(c, j);
            bool lower = (lane & j) == 0;
            bool desc  = (lane & k) == 0;
            c = (lower == desc) ? kmax(c, o) : kmin(c, o);
        }
    }
}
__device__ __forceinline__ void bimerge32(u64& L, int lane) {
#pragma unroll
    for (int j = 16; j > 0; j >>= 1) {
        u64 o = shflx(L, j);
        bool lower = (lane & j) == 0;
        L = lower ? kmax(L, o) : kmin(L, o);
    }
}
__device__ __forceinline__ void merge64(u64& L0, u64& L1, u64 c, int lane) {
    sort32(c, lane);                 // desc
    u64 cr = shflx(c, 31);           // asc
    L1 = kmax(L1, cr);               // top-32 of L1∪c (bitonic)
    bimerge32(L1, lane);             // -> sorted desc
    u64 l1r = shflx(L1, 31);         // asc; (L0 desc | l1r asc) = bitonic-64
    u64 hi = kmax(L0, l1r);
    u64 lo = kmin(L0, l1r);
    bimerge32(hi, lane);
    bimerge32(lo, lane);
    L0 = hi; L1 = lo;
}

// ---------------------------------------------------------------------------
// Kernel 4a: BALLOT-FREE scan. Each lane keeps a private sorted top-12 of its
// stripe (branch-free insertion chain); no warp sync in the hot loop, so
// loads pipeline freely. End of row: 12 register batches -> merge64 -> top-64.
// ---------------------------------------------------------------------------
#define LANE_K 12

__global__ __launch_bounds__(256)
void topk_scan_kernel()
{
    const int warp = threadIdx.x >> 5;
    const int lane = threadIdx.x & 31;
    const int row  = blockIdx.x * 8 + warp;
    const float* rp = g_sim + (size_t)row * M_KV;

    u64 r[LANE_K];
    const u64 SENTK = (u64)ordf(-3.0e38f) << 32;
#pragma unroll
    for (int j = 0; j < LANE_K; j++) r[j] = SENTK;
    float tmin = -3.0e38f;

    for (int base = 0; base < M_KV; base += 512) {
        float4 v0 = *(const float4*)(rp + base +       lane * 4);
        float4 v1 = *(const float4*)(rp + base + 128 + lane * 4);
        float4 v2 = *(const float4*)(rp + base + 256 + lane * 4);
        float4 v3 = *(const float4*)(rp + base + 384 + lane * 4);
        float c[16] = {v0.x, v0.y, v0.z, v0.w, v1.x, v1.y, v1.z, v1.w,
                       v2.x, v2.y, v2.z, v2.w, v3.x, v3.y, v3.z, v3.w};
#pragma unroll
        for (int g = 0; g < 4; g++) {
            float gm = fmaxf(fmaxf(c[g*4], c[g*4+1]), fmaxf(c[g*4+2], c[g*4+3]));
            if (gm >= tmin) {          // per-lane guard only; no warp sync
#pragma unroll
                for (int q = 0; q < 4; q++) {
                    float cv = c[g*4 + q];
                    if (cv >= tmin) {
                        int col = base + g * 128 + lane * 4 + q;
                        u64 k = make_key(cv, col);
                        if (k > r[LANE_K - 1]) {
                            u64 cur = k;
#pragma unroll
                            for (int j = 0; j < LANE_K; j++) {
                                u64 mx = kmax(r[j], cur);
                                cur  = kmin(r[j], cur);
                                r[j] = mx;
                            }
                            tmin = key_val(r[LANE_K - 1]);
                        }
                    }
                }
            }
        }
    }

    // reduce 32 lanes x 12 keys -> top-64 (each r[j] is a warp-wide batch)
    u64 L0 = SENTK, L1 = SENTK;
#pragma unroll
    for (int j = 0; j < LANE_K; j++)
        merge64(L0, L1, r[j], lane);

    g_cand[(size_t)row * 64 + lane]      = (int)(~(u32)L0);
    g_cand[(size_t)row * 64 + lane + 32] = (int)(~(u32)L1);
}

// ---------------------------------------------------------------------------
// Kernel 4b: sequential-fp32 re-rank of the 64 candidates (bit-identical
// arithmetic), exact top-32 select, temperature softmax, write outputs.
// ---------------------------------------------------------------------------
#define TK_WARPS 4

__global__ __launch_bounds__(128)
void topk_rerank_kernel(float* __restrict__ out, int out_size)
{
    __shared__ int   scid[TK_WARPS][64];
    __shared__ float ssfx[TK_WARPS][256];
    __shared__ float stile[TK_WARPS][32][65];
    const unsigned FULL = 0xffffffffu;
    const int warp = threadIdx.x >> 5;
    const int lane = threadIdx.x & 31;
    const int row  = blockIdx.x * TK_WARPS + warp;
    int* cid = scid[warp];
    float* sfx = ssfx[warp];

    int c0i = g_cand[(size_t)row * 64 + lane];
    int c1i = g_cand[(size_t)row * 64 + lane + 32];
    cid[lane]      = c0i;
    cid[lane + 32] = c1i;
    {
        float4 a = *(const float4*)(g_fxn + (size_t)row * DIM + lane * 8);
        float4 b = *(const float4*)(g_fxn + (size_t)row * DIM + lane * 8 + 4);
        *(float4*)(sfx + lane * 8)     = a;
        *(float4*)(sfx + lane * 8 + 4) = b;
    }
    __syncwarp();

    float p0 = 0.0f, p1 = 0.0f;
    for (int c8 = 0; c8 < 8; c8++) {
        const int k0 = c8 * 32;
#pragma unroll
        for (int it = 0; it < 16; it++) {
            int r  = it * 4 + (lane >> 3);
            int f4 = lane & 7;
            float4 v = *(const float4*)(g_fyn + (size_t)cid[r] * DIM + k0 + f4 * 4);
            stile[warp][f4 * 4 + 0][r] = v.x;
            stile[warp][f4 * 4 + 1][r] = v.y;
            stile[warp][f4 * 4 + 2][r] = v.z;
            stile[warp][f4 * 4 + 3][r] = v.w;
        }
        __syncwarp();
#pragma unroll
        for (int kk = 0; kk < 32; kk++) {
            float a = sfx[k0 + kk];
            p0 = fmaf(a, stile[warp][kk][lane],      p0);
            p1 = fmaf(a, stile[warp][kk][lane + 32], p1);
        }
        __syncwarp();
    }
    u64 ex0 = make_key(p0, c0i);
    u64 ex1 = make_key(p1, c1i);

    sort32(ex0, lane);
    sort32(ex1, lane);
    u64 r1 = shflx(ex1, 31);
    ex0 = kmax(ex0, r1);
    bimerge32(ex0, lane);

    float v   = key_val(ex0);
    int   idx = (int)(~(u32)ex0);
    float top = __shfl_sync(FULL, v, 0);
    float e = expf((v - top) / TAU_F);
    float s = e;
#pragma unroll
    for (int o = 16; o > 0; o >>= 1) s += __shfl_xor_sync(FULL, s, o);
    float soft = e / s;

    out[(size_t)row * KNB + lane] = soft;
    if (out_size >= 2 * N_Q * KNB)
        out[(size_t)N_Q * KNB + (size_t)row * KNB + lane] = (float)idx;
}

// ---------------------------------------------------------------------------
extern "C" void kernel_launch(void* const* d_in, const int* in_sizes, int n_in,
                              void* d_out, int out_size)
{
    const float* x = (const float*)d_in[0];
    const float* y = (const float*)d_in[1];
    const float* W = (const float*)d_in[2];
    const float* b = (const float*)d_in[3];
    float* out = (float*)d_out;
    (void)in_sizes; (void)n_in;

    cudaFuncSetAttribute(sim_mma_kernel,
                         cudaFuncAttributeMaxDynamicSharedMemorySize, SIM_SMEM);

    feat_gemm_kernel<<<dim3(DIM / FBN, (N_Q + M_KV) / FBM), 256>>>(x, y, W, b);
    normalize_split_kernel<<<N_Q + M_KV, 256>>>();
    sim_mma_kernel<<<dim3(M_KV / SBN, N_Q / SBM), 256, SIM_SMEM>>>();
    topk_scan_kernel<<<N_Q / 8, 256>>>();
    topk_rerank_kernel<<<N_Q / TK_WARPS, 128>>>(out, out_size);
}

// round 14
// speedup vs baseline: 1.7482x; 1.7482x over previous
#include <cuda_runtime.h>
#include <cuda_bf16.h>
#include <math.h>
#include <stdint.h>

#define N_Q   8192
#define M_KV  8192
#define DIM   256
#define KNB   32
#define TAU_F 0.07f
#define EPS_F 1e-8f

#define KCAT  768    // 3 split-term segments x 256  (hh + hm + mh)
#define NTILE 128    // 64-col tiles per row

// ---------------- scratch (device globals; allocation-free) ----------------
__device__ float g_F[16384 * 256];                          // 16 MB features pre-norm
__device__ float g_fxn[(size_t)N_Q * DIM];                  // 8 MB fp32 normalized x
__device__ float g_fyn[(size_t)M_KV * DIM];                 // 8 MB fp32 normalized y
__device__ __nv_bfloat16 g_axc[(size_t)N_Q * KCAT];         // 12 MB A concat splits (h,h,m)
__device__ __nv_bfloat16 g_byc[(size_t)M_KV * KCAT];        // 12 MB B concat splits (h,m,h)
__device__ float g_sim[(size_t)N_Q * M_KV];                 // 256 MB approx similarity
__device__ float g_rtm[(size_t)N_Q * NTILE];                // 4 MB per-row 64-col tile maxes
__device__ int   g_cand[(size_t)N_Q * 64];                  // 2 MB top-64 candidate ids (-1 = none)

typedef unsigned long long u64;
typedef unsigned int u32;

// ---------------- f32x2 helpers (feat GEMM) ----------------
__device__ __forceinline__ u64 pk2(float lo, float hi) {
    u64 r; asm("mov.b64 %0, {%1, %2};" : "=l"(r) : "f"(lo), "f"(hi)); return r;
}
__device__ __forceinline__ void unpk2(u64 p, float& lo, float& hi) {
    asm("mov.b64 {%0, %1}, %2;" : "=f"(lo), "=f"(hi) : "l"(p));
}
__device__ __forceinline__ void ffma2(u64& d, u64 a, u64 b) {
    asm("fma.rn.f32x2 %0, %1, %2, %0;" : "+l"(d) : "l"(a), "l"(b));
}

// ---------------------------------------------------------------------------
// Kernel 1: F = [x;y] @ W^T + b   (fp32 exact; R1 body — best measured)
// ---------------------------------------------------------------------------
#define FBM 128
#define FBN 128
#define FBK 16
#define FSST 132

__global__ __launch_bounds__(256, 2)
void feat_gemm_kernel(const float* __restrict__ x, const float* __restrict__ y,
                      const float* __restrict__ W, const float* __restrict__ bias)
{
    __shared__ float As[FBK * FSST];
    __shared__ float Bs[FBK * FSST];
    const int tid = threadIdx.x;
    const int tr  = tid >> 4;
    const int tc  = tid & 15;
    const int r0  = blockIdx.y * FBM;
    const int c0  = blockIdx.x * FBN;

    u64 acc[8][4];
#pragma unroll
    for (int i = 0; i < 8; i++)
#pragma unroll
        for (int j = 0; j < 4; j++) acc[i][j] = 0ull;

    for (int k0 = 0; k0 < DIM; k0 += FBK) {
#pragma unroll
        for (int ld = 0; ld < 2; ld++) {
            int pos = tid + ld * 256;
            int r   = pos >> 2;
            int kg  = pos & 3;
            int gr  = r0 + r;
            const float* src = (gr < N_Q) ? (x + (size_t)gr * DIM)
                                          : (y + (size_t)(gr - N_Q) * DIM);
            float4 v = *(const float4*)(src + k0 + kg * 4);
            As[(kg * 4 + 0) * FSST + r] = v.x;
            As[(kg * 4 + 1) * FSST + r] = v.y;
            As[(kg * 4 + 2) * FSST + r] = v.z;
            As[(kg * 4 + 3) * FSST + r] = v.w;
        }
#pragma unroll
        for (int ld = 0; ld < 2; ld++) {
            int pos = tid + ld * 256;
            int c   = pos >> 2;
            int kg  = pos & 3;
            float4 v = *(const float4*)(W + (size_t)(c0 + c) * DIM + k0 + kg * 4);
            Bs[(kg * 4 + 0) * FSST + c] = v.x;
            Bs[(kg * 4 + 1) * FSST + c] = v.y;
            Bs[(kg * 4 + 2) * FSST + c] = v.z;
            Bs[(kg * 4 + 3) * FSST + c] = v.w;
        }
        __syncthreads();
#pragma unroll
        for (int kk = 0; kk < FBK; kk++) {
            const float* ar = As + kk * FSST + tr * 8;
            const u64*   br = (const u64*)(Bs + kk * FSST + tc * 8);
            float4 a0 = *(const float4*)(ar);
            float4 a1 = *(const float4*)(ar + 4);
            u64 b0 = br[0], b1 = br[1], b2 = br[2], b3 = br[3];
            float av[8] = {a0.x, a0.y, a0.z, a0.w, a1.x, a1.y, a1.z, a1.w};
#pragma unroll
            for (int i = 0; i < 8; i++) {
                u64 ai = pk2(av[i], av[i]);
                ffma2(acc[i][0], ai, b0);
                ffma2(acc[i][1], ai, b1);
                ffma2(acc[i][2], ai, b2);
                ffma2(acc[i][3], ai, b3);
            }
        }
        __syncthreads();
    }

    float bl[8];
#pragma unroll
    for (int u = 0; u < 8; u++) bl[u] = bias[c0 + tc * 8 + u];
#pragma unroll
    for (int i = 0; i < 8; i++) {
        int row = r0 + tr * 8 + i;
        float* dst = g_F + (size_t)row * DIM + c0 + tc * 8;
        float4 w0, w1;
        unpk2(acc[i][0], w0.x, w0.y); unpk2(acc[i][1], w0.z, w0.w);
        unpk2(acc[i][2], w1.x, w1.y); unpk2(acc[i][3], w1.z, w1.w);
        w0.x += bl[0]; w0.y += bl[1]; w0.z += bl[2]; w0.w += bl[3];
        w1.x += bl[4]; w1.y += bl[5]; w1.z += bl[6]; w1.w += bl[7];
        *(float4*)dst       = w0;
        *(float4*)(dst + 4) = w1;
    }
}

// ---------------------------------------------------------------------------
// Kernel 2: L2-normalize rows of F; store fp32 (for sequential re-rank) and
// the bf16 split concat operands:  A segs (h,h,m)  B segs (h,m,h)
// ---------------------------------------------------------------------------
__global__ __launch_bounds__(256)
void normalize_split_kernel()
{
    const int row = blockIdx.x;
    const int t   = threadIdx.x;
    float v = g_F[(size_t)row * DIM + t];
    float sq = v * v;
#pragma unroll
    for (int o = 16; o > 0; o >>= 1) sq += __shfl_xor_sync(0xffffffffu, sq, o);
    __shared__ float ws[8];
    __shared__ float sres;
    if ((t & 31) == 0) ws[t >> 5] = sq;
    __syncthreads();
    if (t < 32) {
        float total = (t < 8) ? ws[t] : 0.0f;
#pragma unroll
        for (int o = 4; o > 0; o >>= 1) total += __shfl_xor_sync(0xffffffffu, total, o);
        if (t == 0) sres = rsqrtf(total + EPS_F);
    }
    __syncthreads();
    float vn = v * sres;

    __nv_bfloat16 h = __float2bfloat16_rn(vn);
    float r1 = vn - __bfloat162float(h);
    __nv_bfloat16 m = __float2bfloat16_rn(r1);

    if (row < N_Q) {
        g_fxn[(size_t)row * DIM + t] = vn;
        __nv_bfloat16* p = g_axc + (size_t)row * KCAT + t;
        p[0*DIM] = h; p[1*DIM] = h; p[2*DIM] = m;
    } else {
        int r = row - N_Q;
        g_fyn[(size_t)r * DIM + t] = vn;
        __nv_bfloat16* p = g_byc + (size_t)r * KCAT + t;
        p[0*DIM] = h; p[1*DIM] = m; p[2*DIM] = h;
    }
}

// ---------------------------------------------------------------------------
// Kernel 3: sim = A_cat @ B_cat^T  (8192 x 8192 x 768) on HMMA.
// Epilogue additionally emits per-row 64-col tile maxes into g_rtm.
// ---------------------------------------------------------------------------
#define SBM 256
#define SBN 128
#define NSTAGE 3
#define A_STG (SBM * 128)
#define B_STG (SBN * 128)
#define STG   (A_STG + B_STG)
#define SIM_SMEM (NSTAGE * STG)       // 144 KB
#define NKSTAGES (KCAT / 64)          // 12

#define SWZ(o) ((o) ^ (((o) >> 3) & 0x70))

__device__ __forceinline__ u32 s2u(const void* p) {
    u32 a; asm("{ .reg .u64 t; cvta.to.shared.u64 t, %1; cvt.u32.u64 %0, t; }"
               : "=r"(a) : "l"(p)); return a;
}
__device__ __forceinline__ void cp16(u32 dst, const void* src) {
    asm volatile("cp.async.cg.shared.global [%0], [%1], 16;"
                 :: "r"(dst), "l"(src) : "memory");
}
__device__ __forceinline__ void ldsm4(u32* r, u32 addr) {
    asm volatile("ldmatrix.sync.aligned.m8n8.x4.shared.b16 {%0,%1,%2,%3}, [%4];"
                 : "=r"(r[0]), "=r"(r[1]), "=r"(r[2]), "=r"(r[3]) : "r"(addr));
}
__device__ __forceinline__ void mma16816(float* c, const u32* a, const u32* b) {
    asm volatile(
        "mma.sync.aligned.m16n8k16.row.col.f32.bf16.bf16.f32 "
        "{%0,%1,%2,%3}, {%4,%5,%6,%7}, {%8,%9}, {%0,%1,%2,%3};"
        : "+f"(c[0]), "+f"(c[1]), "+f"(c[2]), "+f"(c[3])
        : "r"(a[0]), "r"(a[1]), "r"(a[2]), "r"(a[3]), "r"(b[0]), "r"(b[1]));
}

__global__ __launch_bounds__(256, 1)
void sim_mma_kernel()
{
    extern __shared__ char dyn[];
    const u32 sbase = s2u(dyn);
    const int tid  = threadIdx.x;
    const int wid  = tid >> 5;
    const int lane = tid & 31;
    const int wm   = wid >> 1;
    const int wn   = wid & 1;
    const int r0   = blockIdx.y * SBM;
    const int c0   = blockIdx.x * SBN;

    float acc[4][8][4];
#pragma unroll
    for (int i = 0; i < 4; i++)
#pragma unroll
        for (int j = 0; j < 8; j++)
#pragma unroll
            for (int q = 0; q < 4; q++) acc[i][j][q] = 0.0f;

    auto loadStage = [&](int s) {
        const int buf = s % NSTAGE;
        const u32 sA = sbase + buf * STG;
        const u32 sB = sA + A_STG;
        const __nv_bfloat16* gA = g_axc + (size_t)r0 * KCAT + s * 64;
        const __nv_bfloat16* gB = g_byc + (size_t)c0 * KCAT + s * 64;
#pragma unroll
        for (int i = 0; i < 8; i++) {
            int id = tid + i * 256;
            int r = id >> 3, kc = id & 7;
            cp16(sA + SWZ(r * 128 + kc * 16), gA + (size_t)r * KCAT + kc * 8);
        }
#pragma unroll
        for (int i = 0; i < 4; i++) {
            int id = tid + i * 256;
            int r = id >> 3, kc = id & 7;
            cp16(sB + SWZ(r * 128 + kc * 16), gB + (size_t)r * KCAT + kc * 8);
        }
        asm volatile("cp.async.commit_group;" ::: "memory");
    };

    loadStage(0);
    loadStage(1);

    for (int s = 0; s < NKSTAGES; s++) {
        if (s + 2 < NKSTAGES)
            asm volatile("cp.async.wait_group 1;" ::: "memory");
        else
            asm volatile("cp.async.wait_group 0;" ::: "memory");
        __syncthreads();
        if (s + 2 < NKSTAGES) loadStage(s + 2);

        const int buf = s % NSTAGE;
        const u32 sA = sbase + buf * STG;
        const u32 sB = sA + A_STG;

#pragma unroll
        for (int ks = 0; ks < 4; ks++) {
            u32 afr[4][4], bfr[4][4];
#pragma unroll
            for (int mt = 0; mt < 4; mt++) {
                int mr = wm * 64 + mt * 16 + (lane & 15);
                int kb = ks * 32 + (lane >> 4) * 16;
                ldsm4(afr[mt], sA + SWZ(mr * 128 + kb));
            }
#pragma unroll
            for (int np = 0; np < 4; np++) {
                int nr = wn * 64 + np * 16 + ((lane >> 4) & 1) * 8 + (lane & 7);
                int kb = ks * 32 + ((lane >> 3) & 1) * 16;
                ldsm4(bfr[np], sB + SWZ(nr * 128 + kb));
            }
#pragma unroll
            for (int mt = 0; mt < 4; mt++)
#pragma unroll
                for (int nt = 0; nt < 8; nt++)
                    mma16816(acc[mt][nt], afr[mt], &bfr[nt >> 1][(nt & 1) * 2]);
        }
    }

#pragma unroll
    for (int mt = 0; mt < 4; mt++) {
        int rlo = r0 + wm * 64 + mt * 16 + (lane >> 2);
#pragma unroll
        for (int nt = 0; nt < 8; nt++) {
            int col = c0 + wn * 64 + nt * 8 + (lane & 3) * 2;
            float2 v0 = make_float2(acc[mt][nt][0], acc[mt][nt][1]);
            float2 v1 = make_float2(acc[mt][nt][2], acc[mt][nt][3]);
            *(float2*)(g_sim + (size_t)rlo * M_KV + col)       = v0;
            *(float2*)(g_sim + (size_t)(rlo + 8) * M_KV + col) = v1;
        }
    }

    // ---- per-row 64-col tile maxes (warp fragment = 64 rows x 64 cols) ----
    const int tile_id = blockIdx.x * 2 + wn;
#pragma unroll
    for (int mt = 0; mt < 4; mt++) {
        float m0 = -3.0e38f, m1 = -3.0e38f;
#pragma unroll
        for (int nt = 0; nt < 8; nt++) {
            m0 = fmaxf(m0, fmaxf(acc[mt][nt][0], acc[mt][nt][1]));
            m1 = fmaxf(m1, fmaxf(acc[mt][nt][2], acc[mt][nt][3]));
        }
        m0 = fmaxf(m0, __shfl_xor_sync(0xffffffffu, m0, 1));
        m0 = fmaxf(m0, __shfl_xor_sync(0xffffffffu, m0, 2));
        m1 = fmaxf(m1, __shfl_xor_sync(0xffffffffu, m1, 1));
        m1 = fmaxf(m1, __shfl_xor_sync(0xffffffffu, m1, 2));
        if ((lane & 3) == 0) {
            int rlo = r0 + wm * 64 + mt * 16 + (lane >> 2);
            g_rtm[(size_t)rlo * NTILE + tile_id]       = m0;
            g_rtm[(size_t)(rlo + 8) * NTILE + tile_id] = m1;
        }
    }
}

// ---------------------------------------------------------------------------
// top-k helpers
// ---------------------------------------------------------------------------
__device__ __forceinline__ u32 ordf(float f) {
    u32 b = __float_as_uint(f);
    return (b & 0x80000000u) ? ~b : (b | 0x80000000u);
}
__device__ __forceinline__ float key_val(u64 k) {
    u32 o = (u32)(k >> 32);
    u32 b = (o & 0x80000000u) ? (o ^ 0x80000000u) : ~o;
    return __uint_as_float(b);
}
__device__ __forceinline__ u64 make_key(float v, int idx) {
    return ((u64)ordf(v) << 32) | (u32)(~(u32)idx);
}
__device__ __forceinline__ u64 kmax(u64 a, u64 b) { return a > b ? a : b; }
__device__ __forceinline__ u64 kmin(u64 a, u64 b) { return a < b ? a : b; }
__device__ __forceinline__ u64 shflx(u64 v, int m) {
    return __shfl_xor_sync(0xffffffffu, v, m);
}
__device__ __forceinline__ void sort32(u64& c, int lane) {
#pragma unroll
    for (int k = 2; k <= 32; k <<= 1) {
#pragma unroll
        for (int j = k >> 1; j > 0; j >>= 1) {
            u64 o = shflx(c, j);
            bool lower = (lane & j) == 0;
            bool desc  = (lane & k) == 0;
            c = (lower == desc) ? kmax(c, o) : kmin(c, o);
        }
    }
}
__device__ __forceinline__ void bimerge32(u64& L, int lane) {
#pragma unroll
    for (int j = 16; j > 0; j >>= 1) {
        u64 o = shflx(L, j);
        bool lower = (lane & j) == 0;
        L = lower ? kmax(L, o) : kmin(L, o);
    }
}
// merge sorted-desc top-32 list L with batch c (unsorted); L stays sorted.
__device__ __forceinline__ void merge32(u64& L, u64 c, int lane) {
    sort32(c, lane);
    u64 cr = shflx(c, 31);
    L = kmax(L, cr);
    bimerge32(L, lane);
}
// merge sorted-desc 64-list with 32 new candidates; keep top-64 sorted desc.
__device__ __forceinline__ void merge64(u64& L0, u64& L1, u64 c, int lane) {
    sort32(c, lane);                 // desc
    u64 cr = shflx(c, 31);           // asc
    L1 = kmax(L1, cr);               // top-32 of L1∪c (bitonic)
    bimerge32(L1, lane);             // -> sorted desc
    u64 l1r = shflx(L1, 31);         // asc; (L0 desc | l1r asc) = bitonic-64
    u64 hi = kmax(L0, l1r);
    u64 lo = kmin(L0, l1r);
    bimerge32(hi, lane);
    bimerge32(lo, lane);
    L0 = hi; L1 = lo;
}

// ---------------------------------------------------------------------------
// Kernel 4a: tile-max-guided scan.
// v0 = 32nd-largest of the row's 128 tile maxes minus a 1e-4 safety margin
// (covers bf16-split approx error with 10x headroom). Guarantees >= 32
// genuine candidates; sentinels are stored as -1 (NOT a duplicate id).
// ---------------------------------------------------------------------------
__global__ __launch_bounds__(256)
void topk_scan_kernel()
{
    __shared__ u64 sbuf[8][64];
    const unsigned FULL = 0xffffffffu;
    const int warp = threadIdx.x >> 5;
    const int lane = threadIdx.x & 31;
    const int row  = blockIdx.x * 8 + warp;
    u64* buf = sbuf[warp];
    const float* rp = g_sim + (size_t)row * M_KV;

    // load 4 tile maxes per lane (tile t lives at lane t>>2, component t&3)
    float4 rv = *(const float4*)(g_rtm + (size_t)row * NTILE + lane * 4);
    float rtmreg[4] = {rv.x, rv.y, rv.z, rv.w};

    // v0 = 32nd-largest tile max, minus approx-error safety margin
    const u64 SENTK = (u64)ordf(-3.0e38f) << 32;
    u64 TL = SENTK;
#pragma unroll
    for (int j = 0; j < 4; j++) {
        u64 c = (u64)ordf(rtmreg[j]) << 32;
        merge32(TL, c, lane);
    }
    const float v0 = key_val(__shfl_sync(FULL, TL, 31)) - 1e-4f;

    u64 L0 = SENTK, L1 = SENTK;
    float mn = v0;
    int cnt = 0;

    for (int tb = 0; tb < 32; tb++) {
#pragma unroll
        for (int j = 0; j < 4; j++) {
            float rtm = __shfl_sync(FULL, rtmreg[j], tb);
            if (rtm < mn) continue;                 // warp-uniform skip
            const int t = tb * 4 + j;
            float2 e = *(const float2*)(rp + t * 64 + lane * 2);
#pragma unroll
            for (int q = 0; q < 2; q++) {
                float cv = q ? e.y : e.x;
                unsigned bal = __ballot_sync(FULL, cv >= mn);
                if (bal) {
                    bool mine = (cv >= mn);
                    int pos = cnt + __popc(bal & ((1u << lane) - 1));
                    if (mine) buf[pos] = make_key(cv, t * 64 + lane * 2 + q);
                    cnt += __popc(bal);
                    while (cnt >= 32) {
                        __syncwarp();
                        u64 cd = buf[lane];
                        if (lane < cnt - 32) buf[lane] = buf[32 + lane];
                        __syncwarp();
                        cnt -= 32;
                        merge64(L0, L1, cd, lane);
                        mn = fmaxf(v0, key_val(__shfl_sync(FULL, L1, 31)));
                    }
                }
            }
        }
    }
    if (cnt > 0) {
        __syncwarp();
        u64 cd = (lane < cnt) ? buf[lane] : 0ull;
        merge64(L0, L1, cd, lane);
    }

    // store raw ids; sentinel slots decode to -1 and are rejected in rerank
    g_cand[(size_t)row * 64 + lane]      = (int)(~(u32)L0);
    g_cand[(size_t)row * 64 + lane + 32] = (int)(~(u32)L1);
}

// ---------------------------------------------------------------------------
// Kernel 4b: sequential-fp32 re-rank of the candidates (bit-identical
// arithmetic). Invalid (-1) slots get key 0 so they can never enter the
// top-32 (>= 32 genuine candidates always exist). Exact top-32 select,
// temperature softmax, write outputs.
// ---------------------------------------------------------------------------
#define TK_WARPS 4

__global__ __launch_bounds__(128)
void topk_rerank_kernel(float* __restrict__ out, int out_size)
{
    __shared__ int   scid[TK_WARPS][64];
    __shared__ float ssfx[TK_WARPS][256];
    __shared__ float stile[TK_WARPS][32][65];
    const unsigned FULL = 0xffffffffu;
    const int warp = threadIdx.x >> 5;
    const int lane = threadIdx.x & 31;
    const int row  = blockIdx.x * TK_WARPS + warp;
    int* cid = scid[warp];
    float* sfx = ssfx[warp];

    int c0i = g_cand[(size_t)row * 64 + lane];
    int c1i = g_cand[(size_t)row * 64 + lane + 32];
    const bool ok0 = ((u32)c0i < (u32)M_KV);
    const bool ok1 = ((u32)c1i < (u32)M_KV);
    cid[lane]      = ok0 ? c0i : 0;     // clamped for loads only
    cid[lane + 32] = ok1 ? c1i : 0;
    {
        float4 a = *(const float4*)(g_fxn + (size_t)row * DIM + lane * 8);
        float4 b = *(const float4*)(g_fxn + (size_t)row * DIM + lane * 8 + 4);
        *(float4*)(sfx + lane * 8)     = a;
        *(float4*)(sfx + lane * 8 + 4) = b;
    }
    __syncwarp();

    float p0 = 0.0f, p1 = 0.0f;
    for (int c8 = 0; c8 < 8; c8++) {
        const int k0 = c8 * 32;
#pragma unroll
        for (int it = 0; it < 16; it++) {
            int r  = it * 4 + (lane >> 3);
            int f4 = lane & 7;
            float4 v = *(const float4*)(g_fyn + (size_t)cid[r] * DIM + k0 + f4 * 4);
            stile[warp][f4 * 4 + 0][r] = v.x;
            stile[warp][f4 * 4 + 1][r] = v.y;
            stile[warp][f4 * 4 + 2][r] = v.z;
            stile[warp][f4 * 4 + 3][r] = v.w;
        }
        __syncwarp();
#pragma unroll
        for (int kk = 0; kk < 32; kk++) {
            float a = sfx[k0 + kk];
            p0 = fmaf(a, stile[warp][kk][lane],      p0);
            p1 = fmaf(a, stile[warp][kk][lane + 32], p1);
        }
        __syncwarp();
    }
    u64 ex0 = ok0 ? make_key(p0, c0i) : 0ull;   // sentinels: minimal key
    u64 ex1 = ok1 ? make_key(p1, c1i) : 0ull;

    sort32(ex0, lane);
    sort32(ex1, lane);
    u64 r1 = shflx(ex1, 31);
    ex0 = kmax(ex0, r1);
    bimerge32(ex0, lane);

    float v   = key_val(ex0);
    int   idx = (int)(~(u32)ex0);
    float top = __shfl_sync(FULL, v, 0);
    float e = expf((v - top) / TAU_F);
    float s = e;
#pragma unroll
    for (int o = 16; o > 0; o >>= 1) s += __shfl_xor_sync(FULL, s, o);
    float soft = e / s;

    out[(size_t)row * KNB + lane] = soft;
    if (out_size >= 2 * N_Q * KNB)
        out[(size_t)N_Q * KNB + (size_t)row * KNB + lane] = (float)idx;
}

// ---------------------------------------------------------------------------
extern "C" void kernel_launch(void* const* d_in, const int* in_sizes, int n_in,
                              void* d_out, int out_size)
{
    const float* x = (const float*)d_in[0];
    const float* y = (const float*)d_in[1];
    const float* W = (const float*)d_in[2];
    const float* b = (const float*)d_in[3];
    float* out = (float*)d_out;
    (void)in_sizes; (void)n_in;

    cudaFuncSetAttribute(sim_mma_kernel,
                         cudaFuncAttributeMaxDynamicSharedMemorySize, SIM_SMEM);

    feat_gemm_kernel<<<dim3(DIM / FBN, (N_Q + M_KV) / FBM), 256>>>(x, y, W, b);
    normalize_split_kernel<<<N_Q + M_KV, 256>>>();
    sim_mma_kernel<<<dim3(M_KV / SBN, N_Q / SBM), 256, SIM_SMEM>>>();
    topk_scan_kernel<<<N_Q / 8, 256>>>();
    topk_rerank_kernel<<<N_Q / TK_WARPS, 128>>>(out, out_size);
}

// round 15
// speedup vs baseline: 1.8571x; 1.0623x over previous
#include <cuda_runtime.h>
#include <cuda_bf16.h>
#include <math.h>
#include <stdint.h>

#define N_Q   8192
#define M_KV  8192
#define DIM   256
#define KNB   32
#define TAU_F 0.07f
#define EPS_F 1e-8f

#define NTILE 128    // 64-col tiles per row

// ---------------- scratch (device globals; allocation-free) ----------------
__device__ float g_F[16384 * 256];                          // 16 MB features pre-norm
__device__ float g_fxn[(size_t)N_Q * DIM];                  // 8 MB fp32 normalized x
__device__ float g_fyn[(size_t)M_KV * DIM];                 // 8 MB fp32 normalized y
__device__ __nv_bfloat16 g_ah[(size_t)N_Q * DIM];           // 4 MB x split hi
__device__ __nv_bfloat16 g_am[(size_t)N_Q * DIM];           // 4 MB x split mid
__device__ __nv_bfloat16 g_bh[(size_t)M_KV * DIM];          // 4 MB y split hi
__device__ __nv_bfloat16 g_bm[(size_t)M_KV * DIM];          // 4 MB y split mid
__device__ float g_sim[(size_t)N_Q * M_KV];                 // 256 MB approx similarity
__device__ float g_rtm[(size_t)N_Q * NTILE];                // 4 MB per-row 64-col tile maxes
__device__ int   g_cand[(size_t)N_Q * 64];                  // 2 MB top-64 candidate ids (-1 = none)

typedef unsigned long long u64;
typedef unsigned int u32;

// ---------------- f32x2 helpers (feat GEMM) ----------------
__device__ __forceinline__ u64 pk2(float lo, float hi) {
    u64 r; asm("mov.b64 %0, {%1, %2};" : "=l"(r) : "f"(lo), "f"(hi)); return r;
}
__device__ __forceinline__ void unpk2(u64 p, float& lo, float& hi) {
    asm("mov.b64 {%0, %1}, %2;" : "=f"(lo), "=f"(hi) : "l"(p));
}
__device__ __forceinline__ void ffma2(u64& d, u64 a, u64 b) {
    asm("fma.rn.f32x2 %0, %1, %2, %0;" : "+l"(d) : "l"(a), "l"(b));
}

// ---------------------------------------------------------------------------
// Kernel 1: F = [x;y] @ W^T + b   (fp32 exact; R1 body — best measured)
// ---------------------------------------------------------------------------
#define FBM 128
#define FBN 128
#define FBK 16
#define FSST 132

__global__ __launch_bounds__(256, 2)
void feat_gemm_kernel(const float* __restrict__ x, const float* __restrict__ y,
                      const float* __restrict__ W, const float* __restrict__ bias)
{
    __shared__ float As[FBK * FSST];
    __shared__ float Bs[FBK * FSST];
    const int tid = threadIdx.x;
    const int tr  = tid >> 4;
    const int tc  = tid & 15;
    const int r0  = blockIdx.y * FBM;
    const int c0  = blockIdx.x * FBN;

    u64 acc[8][4];
#pragma unroll
    for (int i = 0; i < 8; i++)
#pragma unroll
        for (int j = 0; j < 4; j++) acc[i][j] = 0ull;

    for (int k0 = 0; k0 < DIM; k0 += FBK) {
#pragma unroll
        for (int ld = 0; ld < 2; ld++) {
            int pos = tid + ld * 256;
            int r   = pos >> 2;
            int kg  = pos & 3;
            int gr  = r0 + r;
            const float* src = (gr < N_Q) ? (x + (size_t)gr * DIM)
                                          : (y + (size_t)(gr - N_Q) * DIM);
            float4 v = *(const float4*)(src + k0 + kg * 4);
            As[(kg * 4 + 0) * FSST + r] = v.x;
            As[(kg * 4 + 1) * FSST + r] = v.y;
            As[(kg * 4 + 2) * FSST + r] = v.z;
            As[(kg * 4 + 3) * FSST + r] = v.w;
        }
#pragma unroll
        for (int ld = 0; ld < 2; ld++) {
            int pos = tid + ld * 256;
            int c   = pos >> 2;
            int kg  = pos & 3;
            float4 v = *(const float4*)(W + (size_t)(c0 + c) * DIM + k0 + kg * 4);
            Bs[(kg * 4 + 0) * FSST + c] = v.x;
            Bs[(kg * 4 + 1) * FSST + c] = v.y;
            Bs[(kg * 4 + 2) * FSST + c] = v.z;
            Bs[(kg * 4 + 3) * FSST + c] = v.w;
        }
        __syncthreads();
#pragma unroll
        for (int kk = 0; kk < FBK; kk++) {
            const float* ar = As + kk * FSST + tr * 8;
            const u64*   br = (const u64*)(Bs + kk * FSST + tc * 8);
            float4 a0 = *(const float4*)(ar);
            float4 a1 = *(const float4*)(ar + 4);
            u64 b0 = br[0], b1 = br[1], b2 = br[2], b3 = br[3];
            float av[8] = {a0.x, a0.y, a0.z, a0.w, a1.x, a1.y, a1.z, a1.w};
#pragma unroll
            for (int i = 0; i < 8; i++) {
                u64 ai = pk2(av[i], av[i]);
                ffma2(acc[i][0], ai, b0);
                ffma2(acc[i][1], ai, b1);
                ffma2(acc[i][2], ai, b2);
                ffma2(acc[i][3], ai, b3);
            }
        }
        __syncthreads();
    }

    float bl[8];
#pragma unroll
    for (int u = 0; u < 8; u++) bl[u] = bias[c0 + tc * 8 + u];
#pragma unroll
    for (int i = 0; i < 8; i++) {
        int row = r0 + tr * 8 + i;
        float* dst = g_F + (size_t)row * DIM + c0 + tc * 8;
        float4 w0, w1;
        unpk2(acc[i][0], w0.x, w0.y); unpk2(acc[i][1], w0.z, w0.w);
        unpk2(acc[i][2], w1.x, w1.y); unpk2(acc[i][3], w1.z, w1.w);
        w0.x += bl[0]; w0.y += bl[1]; w0.z += bl[2]; w0.w += bl[3];
        w1.x += bl[4]; w1.y += bl[5]; w1.z += bl[6]; w1.w += bl[7];
        *(float4*)dst       = w0;
        *(float4*)(dst + 4) = w1;
    }
}

// ---------------------------------------------------------------------------
// Kernel 2: L2-normalize rows of F; store fp32 (for sequential re-rank) and
// separate bf16 split arrays (h, m) for operand-shared MMA.
// ---------------------------------------------------------------------------
__global__ __launch_bounds__(256)
void normalize_split_kernel()
{
    const int row = blockIdx.x;
    const int t   = threadIdx.x;
    float v = g_F[(size_t)row * DIM + t];
    float sq = v * v;
#pragma unroll
    for (int o = 16; o > 0; o >>= 1) sq += __shfl_xor_sync(0xffffffffu, sq, o);
    __shared__ float ws[8];
    __shared__ float sres;
    if ((t & 31) == 0) ws[t >> 5] = sq;
    __syncthreads();
    if (t < 32) {
        float total = (t < 8) ? ws[t] : 0.0f;
#pragma unroll
        for (int o = 4; o > 0; o >>= 1) total += __shfl_xor_sync(0xffffffffu, total, o);
        if (t == 0) sres = rsqrtf(total + EPS_F);
    }
    __syncthreads();
    float vn = v * sres;

    __nv_bfloat16 h = __float2bfloat16_rn(vn);
    float r1 = vn - __bfloat162float(h);
    __nv_bfloat16 m = __float2bfloat16_rn(r1);

    if (row < N_Q) {
        size_t i = (size_t)row * DIM + t;
        g_fxn[i] = vn;
        g_ah[i] = h; g_am[i] = m;
    } else {
        size_t i = (size_t)(row - N_Q) * DIM + t;
        g_fyn[i] = vn;
        g_bh[i] = h; g_bm[i] = m;
    }
}

// ---------------------------------------------------------------------------
// Kernel 3: sim = h·h' + h·m' + m·h' via operand-shared HMMA.
// Per 64-k chunk: load Ah, Am (256x64) + Bh, Bm (128x64) ONCE, issue the 3
// term-MMAs from the same smem (1/3 less L2 traffic than concat layout).
// 256x128 CTA tile, 8 warps of 64x64, 4 k-chunks, 2-stage cp.async pipeline.
// Epilogue writes sim + per-row 64-col tile maxes.
// ---------------------------------------------------------------------------
#define SBM 256
#define SBN 128
#define TILE_A (SBM * 128)            // 32 KB (one split)
#define TILE_B (SBN * 128)            // 16 KB (one split)
#define STG    (2 * TILE_A + 2 * TILE_B)   // 96 KB
#define SIM_SMEM (2 * STG)            // 192 KB
#define NCHUNK 4                      // 4 x 64-k chunks

#define SWZ(o) ((o) ^ (((o) >> 3) & 0x70))

__device__ __forceinline__ u32 s2u(const void* p) {
    u32 a; asm("{ .reg .u64 t; cvta.to.shared.u64 t, %1; cvt.u32.u64 %0, t; }"
               : "=r"(a) : "l"(p)); return a;
}
__device__ __forceinline__ void cp16(u32 dst, const void* src) {
    asm volatile("cp.async.cg.shared.global [%0], [%1], 16;"
                 :: "r"(dst), "l"(src) : "memory");
}
__device__ __forceinline__ void ldsm4(u32* r, u32 addr) {
    asm volatile("ldmatrix.sync.aligned.m8n8.x4.shared.b16 {%0,%1,%2,%3}, [%4];"
                 : "=r"(r[0]), "=r"(r[1]), "=r"(r[2]), "=r"(r[3]) : "r"(addr));
}
__device__ __forceinline__ void mma16816(float* c, const u32* a, const u32* b) {
    asm volatile(
        "mma.sync.aligned.m16n8k16.row.col.f32.bf16.bf16.f32 "
        "{%0,%1,%2,%3}, {%4,%5,%6,%7}, {%8,%9}, {%0,%1,%2,%3};"
        : "+f"(c[0]), "+f"(c[1]), "+f"(c[2]), "+f"(c[3])
        : "r"(a[0]), "r"(a[1]), "r"(a[2]), "r"(a[3]), "r"(b[0]), "r"(b[1]));
}

__global__ __launch_bounds__(256, 1)
void sim_mma_kernel()
{
    extern __shared__ char dyn[];
    const u32 sbase = s2u(dyn);
    const int tid  = threadIdx.x;
    const int wid  = tid >> 5;
    const int lane = tid & 31;
    const int wm   = wid >> 1;
    const int wn   = wid & 1;
    const int r0   = blockIdx.y * SBM;
    const int c0   = blockIdx.x * SBN;

    float acc[4][8][4];
#pragma unroll
    for (int i = 0; i < 4; i++)
#pragma unroll
        for (int j = 0; j < 8; j++)
#pragma unroll
            for (int q = 0; q < 4; q++) acc[i][j][q] = 0.0f;

    auto loadStage = [&](int s) {
        const int buf = s & 1;
        const u32 base = sbase + buf * STG;
        const int k0 = s * 64;
        const __nv_bfloat16* gAh = g_ah + (size_t)r0 * DIM + k0;
        const __nv_bfloat16* gAm = g_am + (size_t)r0 * DIM + k0;
        const __nv_bfloat16* gBh = g_bh + (size_t)c0 * DIM + k0;
        const __nv_bfloat16* gBm = g_bm + (size_t)c0 * DIM + k0;
#pragma unroll
        for (int i = 0; i < 8; i++) {             // A: 256 rows x 8 chunks
            int id = tid + i * 256;
            int r = id >> 3, kc = id & 7;
            u32 so = SWZ((u32)(r * 128 + kc * 16));
            const size_t go = (size_t)r * DIM + kc * 8;
            cp16(base + so,          gAh + go);
            cp16(base + TILE_A + so, gAm + go);
        }
#pragma unroll
        for (int i = 0; i < 4; i++) {             // B: 128 rows x 8 chunks
            int id = tid + i * 256;
            int r = id >> 3, kc = id & 7;
            u32 so = SWZ((u32)(r * 128 + kc * 16));
            const size_t go = (size_t)r * DIM + kc * 8;
            cp16(base + 2 * TILE_A + so,          gBh + go);
            cp16(base + 2 * TILE_A + TILE_B + so, gBm + go);
        }
        asm volatile("cp.async.commit_group;" ::: "memory");
    };

    loadStage(0);
    loadStage(1);

    for (int s = 0; s < NCHUNK; s++) {
        if (s < NCHUNK - 1)
            asm volatile("cp.async.wait_group 1;" ::: "memory");
        else
            asm volatile("cp.async.wait_group 0;" ::: "memory");
        __syncthreads();

        const u32 base = sbase + (s & 1) * STG;
        const u32 sAh = base;
        const u32 sAm = base + TILE_A;
        const u32 sBh = base + 2 * TILE_A;
        const u32 sBm = base + 2 * TILE_A + TILE_B;

#pragma unroll
        for (int ks = 0; ks < 4; ks++) {
            u32 A1[4][4], B1[4][4], B2[4][4];
            const int kbA = ks * 32 + (lane >> 4) * 16;
            const int kbB = ks * 32 + ((lane >> 3) & 1) * 16;
#pragma unroll
            for (int mt = 0; mt < 4; mt++) {
                int mr = wm * 64 + mt * 16 + (lane & 15);
                ldsm4(A1[mt], sAh + SWZ(mr * 128 + kbA));
            }
#pragma unroll
            for (int np = 0; np < 4; np++) {
                int nr = wn * 64 + np * 16 + ((lane >> 4) & 1) * 8 + (lane & 7);
                ldsm4(B1[np], sBh + SWZ(nr * 128 + kbB));
            }
#pragma unroll
            for (int np = 0; np < 4; np++) {
                int nr = wn * 64 + np * 16 + ((lane >> 4) & 1) * 8 + (lane & 7);
                ldsm4(B2[np], sBm + SWZ(nr * 128 + kbB));
            }
            // hh + hm from A=h
#pragma unroll
            for (int mt = 0; mt < 4; mt++)
#pragma unroll
                for (int nt = 0; nt < 8; nt++) {
                    mma16816(acc[mt][nt], A1[mt], &B1[nt >> 1][(nt & 1) * 2]);
                    mma16816(acc[mt][nt], A1[mt], &B2[nt >> 1][(nt & 1) * 2]);
                }
            // mh: reload A=m over A1
#pragma unroll
            for (int mt = 0; mt < 4; mt++) {
                int mr = wm * 64 + mt * 16 + (lane & 15);
                ldsm4(A1[mt], sAm + SWZ(mr * 128 + kbA));
            }
#pragma unroll
            for (int mt = 0; mt < 4; mt++)
#pragma unroll
                for (int nt = 0; nt < 8; nt++)
                    mma16816(acc[mt][nt], A1[mt], &B1[nt >> 1][(nt & 1) * 2]);
        }

        if (s + 2 < NCHUNK) {
            __syncthreads();
            loadStage(s + 2);
        }
    }

#pragma unroll
    for (int mt = 0; mt < 4; mt++) {
        int rlo = r0 + wm * 64 + mt * 16 + (lane >> 2);
#pragma unroll
        for (int nt = 0; nt < 8; nt++) {
            int col = c0 + wn * 64 + nt * 8 + (lane & 3) * 2;
            float2 v0 = make_float2(acc[mt][nt][0], acc[mt][nt][1]);
            float2 v1 = make_float2(acc[mt][nt][2], acc[mt][nt][3]);
            *(float2*)(g_sim + (size_t)rlo * M_KV + col)       = v0;
            *(float2*)(g_sim + (size_t)(rlo + 8) * M_KV + col) = v1;
        }
    }

    // ---- per-row 64-col tile maxes (warp fragment = 64 rows x 64 cols) ----
    const int tile_id = blockIdx.x * 2 + wn;
#pragma unroll
    for (int mt = 0; mt < 4; mt++) {
        float m0 = -3.0e38f, m1 = -3.0e38f;
#pragma unroll
        for (int nt = 0; nt < 8; nt++) {
            m0 = fmaxf(m0, fmaxf(acc[mt][nt][0], acc[mt][nt][1]));
            m1 = fmaxf(m1, fmaxf(acc[mt][nt][2], acc[mt][nt][3]));
        }
        m0 = fmaxf(m0, __shfl_xor_sync(0xffffffffu, m0, 1));
        m0 = fmaxf(m0, __shfl_xor_sync(0xffffffffu, m0, 2));
        m1 = fmaxf(m1, __shfl_xor_sync(0xffffffffu, m1, 1));
        m1 = fmaxf(m1, __shfl_xor_sync(0xffffffffu, m1, 2));
        if ((lane & 3) == 0) {
            int rlo = r0 + wm * 64 + mt * 16 + (lane >> 2);
            g_rtm[(size_t)rlo * NTILE + tile_id]       = m0;
            g_rtm[(size_t)(rlo + 8) * NTILE + tile_id] = m1;
        }
    }
}

// ---------------------------------------------------------------------------
// top-k helpers
// ---------------------------------------------------------------------------
__device__ __forceinline__ u32 ordf(float f) {
    u32 b = __float_as_uint(f);
    return (b & 0x80000000u) ? ~b : (b | 0x80000000u);
}
__device__ __forceinline__ float key_val(u64 k) {
    u32 o = (u32)(k >> 32);
    u32 b = (o & 0x80000000u) ? (o ^ 0x80000000u) : ~o;
    return __uint_as_float(b);
}
__device__ __forceinline__ u64 make_key(float v, int idx) {
    return ((u64)ordf(v) << 32) | (u32)(~(u32)idx);
}
__device__ __forceinline__ u64 kmax(u64 a, u64 b) { return a > b ? a : b; }
__device__ __forceinline__ u64 kmin(u64 a, u64 b) { return a < b ? a : b; }
__device__ __forceinline__ u64 shflx(u64 v, int m) {
    return __shfl_xor_sync(0xffffffffu, v, m);
}
__device__ __forceinline__ void sort32(u64& c, int lane) {
#pragma unroll
    for (int k = 2; k <= 32; k <<= 1) {
#pragma unroll
        for (int j = k >> 1; j > 0; j >>= 1) {
            u64 o = shflx(c, j);
            bool lower = (lane & j) == 0;
            bool desc  = (lane & k) == 0;
            c = (lower == desc) ? kmax(c, o) : kmin(c, o);
        }
    }
}
__device__ __forceinline__ void bimerge32(u64& L, int lane) {
#pragma unroll
    for (int j = 16; j > 0; j >>= 1) {
        u64 o = shflx(L, j);
        bool lower = (lane & j) == 0;
        L = lower ? kmax(L, o) : kmin(L, o);
    }
}
__device__ __forceinline__ void merge32(u64& L, u64 c, int lane) {
    sort32(c, lane);
    u64 cr = shflx(c, 31);
    L = kmax(L, cr);
    bimerge32(L, lane);
}
__device__ __forceinline__ void merge64(u64& L0, u64& L1, u64 c, int lane) {
    sort32(c, lane);                 // desc
    u64 cr = shflx(c, 31);           // asc
    L1 = kmax(L1, cr);               // top-32 of L1∪c (bitonic)
    bimerge32(L1, lane);             // -> sorted desc
    u64 l1r = shflx(L1, 31);         // asc; (L0 desc | l1r asc) = bitonic-64
    u64 hi = kmax(L0, l1r);
    u64 lo = kmin(L0, l1r);
    bimerge32(hi, lane);
    bimerge32(lo, lane);
    L0 = hi; L1 = lo;
}

// ---------------------------------------------------------------------------
// Kernel 4a: tile-max-guided scan (R14, unchanged — 62 us measured).
// ---------------------------------------------------------------------------
__global__ __launch_bounds__(256)
void topk_scan_kernel()
{
    __shared__ u64 sbuf[8][64];
    const unsigned FULL = 0xffffffffu;
    const int warp = threadIdx.x >> 5;
    const int lane = threadIdx.x & 31;
    const int row  = blockIdx.x * 8 + warp;
    u64* buf = sbuf[warp];
    const float* rp = g_sim + (size_t)row * M_KV;

    float4 rv = *(const float4*)(g_rtm + (size_t)row * NTILE + lane * 4);
    float rtmreg[4] = {rv.x, rv.y, rv.z, rv.w};

    const u64 SENTK = (u64)ordf(-3.0e38f) << 32;
    u64 TL = SENTK;
#pragma unroll
    for (int j = 0; j < 4; j++) {
        u64 c = (u64)ordf(rtmreg[j]) << 32;
        merge32(TL, c, lane);
    }
    const float v0 = key_val(__shfl_sync(FULL, TL, 31)) - 1e-4f;

    u64 L0 = SENTK, L1 = SENTK;
    float mn = v0;
    int cnt = 0;

    for (int tb = 0; tb < 32; tb++) {
#pragma unroll
        for (int j = 0; j < 4; j++) {
            float rtm = __shfl_sync(FULL, rtmreg[j], tb);
            if (rtm < mn) continue;                 // warp-uniform skip
            const int t = tb * 4 + j;
            float2 e = *(const float2*)(rp + t * 64 + lane * 2);
#pragma unroll
            for (int q = 0; q < 2; q++) {
                float cv = q ? e.y : e.x;
                unsigned bal = __ballot_sync(FULL, cv >= mn);
                if (bal) {
                    bool mine = (cv >= mn);
                    int pos = cnt + __popc(bal & ((1u << lane) - 1));
                    if (mine) buf[pos] = make_key(cv, t * 64 + lane * 2 + q);
                    cnt += __popc(bal);
                    while (cnt >= 32) {
                        __syncwarp();
                        u64 cd = buf[lane];
                        if (lane < cnt - 32) buf[lane] = buf[32 + lane];
                        __syncwarp();
                        cnt -= 32;
                        merge64(L0, L1, cd, lane);
                        mn = fmaxf(v0, key_val(__shfl_sync(FULL, L1, 31)));
                    }
                }
            }
        }
    }
    if (cnt > 0) {
        __syncwarp();
        u64 cd = (lane < cnt) ? buf[lane] : 0ull;
        merge64(L0, L1, cd, lane);
    }

    g_cand[(size_t)row * 64 + lane]      = (int)(~(u32)L0);
    g_cand[(size_t)row * 64 + lane + 32] = (int)(~(u32)L1);
}

// ---------------------------------------------------------------------------
// Kernel 4b: sequential-fp32 re-rank (R14, unchanged).
// ---------------------------------------------------------------------------
#define TK_WARPS 4

__global__ __launch_bounds__(128)
void topk_rerank_kernel(float* __restrict__ out, int out_size)
{
    __shared__ int   scid[TK_WARPS][64];
    __shared__ float ssfx[TK_WARPS][256];
    __shared__ float stile[TK_WARPS][32][65];
    const unsigned FULL = 0xffffffffu;
    const int warp = threadIdx.x >> 5;
    const int lane = threadIdx.x & 31;
    const int row  = blockIdx.x * TK_WARPS + warp;
    int* cid = scid[warp];
    float* sfx = ssfx[warp];

    int c0i = g_cand[(size_t)row * 64 + lane];
    int c1i = g_cand[(size_t)row * 64 + lane + 32];
    const bool ok0 = ((u32)c0i < (u32)M_KV);
    const bool ok1 = ((u32)c1i < (u32)M_KV);
    cid[lane]      = ok0 ? c0i : 0;
    cid[lane + 32] = ok1 ? c1i : 0;
    {
        float4 a = *(const float4*)(g_fxn + (size_t)row * DIM + lane * 8);
        float4 b = *(const float4*)(g_fxn + (size_t)row * DIM + lane * 8 + 4);
        *(float4*)(sfx + lane * 8)     = a;
        *(float4*)(sfx + lane * 8 + 4) = b;
    }
    __syncwarp();

    float p0 = 0.0f, p1 = 0.0f;
    for (int c8 = 0; c8 < 8; c8++) {
        const int k0 = c8 * 32;
#pragma unroll
        for (int it = 0; it < 16; it++) {
            int r  = it * 4 + (lane >> 3);
            int f4 = lane & 7;
            float4 v = *(const float4*)(g_fyn + (size_t)cid[r] * DIM + k0 + f4 * 4);
            stile[warp][f4 * 4 + 0][r] = v.x;
            stile[warp][f4 * 4 + 1][r] = v.y;
            stile[warp][f4 * 4 + 2][r] = v.z;
            stile[warp][f4 * 4 + 3][r] = v.w;
        }
        __syncwarp();
#pragma unroll
        for (int kk = 0; kk < 32; kk++) {
            float a = sfx[k0 + kk];
            p0 = fmaf(a, stile[warp][kk][lane],      p0);
            p1 = fmaf(a, stile[warp][kk][lane + 32], p1);
        }
        __syncwarp();
    }
    u64 ex0 = ok0 ? make_key(p0, c0i) : 0ull;
    u64 ex1 = ok1 ? make_key(p1, c1i) : 0ull;

    sort32(ex0, lane);
    sort32(ex1, lane);
    u64 r1 = shflx(ex1, 31);
    ex0 = kmax(ex0, r1);
    bimerge32(ex0, lane);

    float v   = key_val(ex0);
    int   idx = (int)(~(u32)ex0);
    float top = __shfl_sync(FULL, v, 0);
    float e = expf((v - top) / TAU_F);
    float s = e;
#pragma unroll
    for (int o = 16; o > 0; o >>= 1) s += __shfl_xor_sync(FULL, s, o);
    float soft = e / s;

    out[(size_t)row * KNB + lane] = soft;
    if (out_size >= 2 * N_Q * KNB)
        out[(size_t)N_Q * KNB + (size_t)row * KNB + lane] = (float)idx;
}

// ---------------------------------------------------------------------------
extern "C" void kernel_launch(void* const* d_in, const int* in_sizes, int n_in,
                              void* d_out, int out_size)
{
    const float* x = (const float*)d_in[0];
    const float* y = (const float*)d_in[1];
    const float* W = (const float*)d_in[2];
    const float* b = (const float*)d_in[3];
    float* out = (float*)d_out;
    (void)in_sizes; (void)n_in;

    cudaFuncSetAttribute(sim_mma_kernel,
                         cudaFuncAttributeMaxDynamicSharedMemorySize, SIM_SMEM);

    feat_gemm_kernel<<<dim3(DIM / FBN, (N_Q + M_KV) / FBM), 256>>>(x, y, W, b);
    normalize_split_kernel<<<N_Q + M_KV, 256>>>();
    sim_mma_kernel<<<dim3(M_KV / SBN, N_Q / SBM), 256, SIM_SMEM>>>();
    topk_scan_kernel<<<N_Q / 8, 256>>>();
    topk_rerank_kernel<<<N_Q / TK_WARPS, 128>>>(out, out_size);
}

// round 16
// speedup vs baseline: 2.1114x; 1.1369x over previous
#include <cuda_runtime.h>
#include <cuda_bf16.h>
#include <math.h>
#include <stdint.h>

#define N_Q   8192
#define M_KV  8192
#define DIM   256
#define KNB   32
#define TAU_F 0.07f
#define EPS_F 1e-8f

#define NTILE 128    // 64-col tiles per row
#define SCAN_MARGIN 1e-3f   // covers 2-term approx error (abs bound 5e-4) 2x

// ---------------- scratch (device globals; allocation-free) ----------------
__device__ float g_F[16384 * 256];                          // 16 MB features pre-norm
__device__ float g_fxn[(size_t)N_Q * DIM];                  // 8 MB fp32 normalized x
__device__ float g_fyn[(size_t)M_KV * DIM];                 // 8 MB fp32 normalized y
__device__ __nv_bfloat16 g_ah[(size_t)N_Q * DIM];           // 4 MB x split hi
__device__ __nv_bfloat16 g_bh[(size_t)M_KV * DIM];          // 4 MB y split hi
__device__ __nv_bfloat16 g_bm[(size_t)M_KV * DIM];          // 4 MB y split mid
__device__ float g_sim[(size_t)N_Q * M_KV];                 // 256 MB approx similarity
__device__ float g_rtm[(size_t)N_Q * NTILE];                // 4 MB per-row 64-col tile maxes
__device__ int   g_cand[(size_t)N_Q * 64];                  // 2 MB top-64 candidate ids (-1 = none)

typedef unsigned long long u64;
typedef unsigned int u32;

// ---------------- f32x2 helpers (feat GEMM) ----------------
__device__ __forceinline__ u64 pk2(float lo, float hi) {
    u64 r; asm("mov.b64 %0, {%1, %2};" : "=l"(r) : "f"(lo), "f"(hi)); return r;
}
__device__ __forceinline__ void unpk2(u64 p, float& lo, float& hi) {
    asm("mov.b64 {%0, %1}, %2;" : "=f"(lo), "=f"(hi) : "l"(p));
}
__device__ __forceinline__ void ffma2(u64& d, u64 a, u64 b) {
    asm("fma.rn.f32x2 %0, %1, %2, %0;" : "+l"(d) : "l"(a), "l"(b));
}

// ---------------------------------------------------------------------------
// Kernel 1: F = [x;y] @ W^T + b   (fp32 exact; R1 body — best measured)
// ---------------------------------------------------------------------------
#define FBM 128
#define FBN 128
#define FBK 16
#define FSST 132

__global__ __launch_bounds__(256, 2)
void feat_gemm_kernel(const float* __restrict__ x, const float* __restrict__ y,
                      const float* __restrict__ W, const float* __restrict__ bias)
{
    __shared__ float As[FBK * FSST];
    __shared__ float Bs[FBK * FSST];
    const int tid = threadIdx.x;
    const int tr  = tid >> 4;
    const int tc  = tid & 15;
    const int r0  = blockIdx.y * FBM;
    const int c0  = blockIdx.x * FBN;

    u64 acc[8][4];
#pragma unroll
    for (int i = 0; i < 8; i++)
#pragma unroll
        for (int j = 0; j < 4; j++) acc[i][j] = 0ull;

    for (int k0 = 0; k0 < DIM; k0 += FBK) {
#pragma unroll
        for (int ld = 0; ld < 2; ld++) {
            int pos = tid + ld * 256;
            int r   = pos >> 2;
            int kg  = pos & 3;
            int gr  = r0 + r;
            const float* src = (gr < N_Q) ? (x + (size_t)gr * DIM)
                                          : (y + (size_t)(gr - N_Q) * DIM);
            float4 v = *(const float4*)(src + k0 + kg * 4);
            As[(kg * 4 + 0) * FSST + r] = v.x;
            As[(kg * 4 + 1) * FSST + r] = v.y;
            As[(kg * 4 + 2) * FSST + r] = v.z;
            As[(kg * 4 + 3) * FSST + r] = v.w;
        }
#pragma unroll
        for (int ld = 0; ld < 2; ld++) {
            int pos = tid + ld * 256;
            int c   = pos >> 2;
            int kg  = pos & 3;
            float4 v = *(const float4*)(W + (size_t)(c0 + c) * DIM + k0 + kg * 4);
            Bs[(kg * 4 + 0) * FSST + c] = v.x;
            Bs[(kg * 4 + 1) * FSST + c] = v.y;
            Bs[(kg * 4 + 2) * FSST + c] = v.z;
            Bs[(kg * 4 + 3) * FSST + c] = v.w;
        }
        __syncthreads();
#pragma unroll
        for (int kk = 0; kk < FBK; kk++) {
            const float* ar = As + kk * FSST + tr * 8;
            const u64*   br = (const u64*)(Bs + kk * FSST + tc * 8);
            float4 a0 = *(const float4*)(ar);
            float4 a1 = *(const float4*)(ar + 4);
            u64 b0 = br[0], b1 = br[1], b2 = br[2], b3 = br[3];
            float av[8] = {a0.x, a0.y, a0.z, a0.w, a1.x, a1.y, a1.z, a1.w};
#pragma unroll
            for (int i = 0; i < 8; i++) {
                u64 ai = pk2(av[i], av[i]);
                ffma2(acc[i][0], ai, b0);
                ffma2(acc[i][1], ai, b1);
                ffma2(acc[i][2], ai, b2);
                ffma2(acc[i][3], ai, b3);
            }
        }
        __syncthreads();
    }

    float bl[8];
#pragma unroll
    for (int u = 0; u < 8; u++) bl[u] = bias[c0 + tc * 8 + u];
#pragma unroll
    for (int i = 0; i < 8; i++) {
        int row = r0 + tr * 8 + i;
        float* dst = g_F + (size_t)row * DIM + c0 + tc * 8;
        float4 w0, w1;
        unpk2(acc[i][0], w0.x, w0.y); unpk2(acc[i][1], w0.z, w0.w);
        unpk2(acc[i][2], w1.x, w1.y); unpk2(acc[i][3], w1.z, w1.w);
        w0.x += bl[0]; w0.y += bl[1]; w0.z += bl[2]; w0.w += bl[3];
        w1.x += bl[4]; w1.y += bl[5]; w1.z += bl[6]; w1.w += bl[7];
        *(float4*)dst       = w0;
        *(float4*)(dst + 4) = w1;
    }
}

// ---------------------------------------------------------------------------
// Kernel 2: L2-normalize rows of F; store fp32 (for sequential re-rank) and
// bf16 splits: x side needs h only, y side needs h and m (2-term GEMM).
// ---------------------------------------------------------------------------
__global__ __launch_bounds__(256)
void normalize_split_kernel()
{
    const int row = blockIdx.x;
    const int t   = threadIdx.x;
    float v = g_F[(size_t)row * DIM + t];
    float sq = v * v;
#pragma unroll
    for (int o = 16; o > 0; o >>= 1) sq += __shfl_xor_sync(0xffffffffu, sq, o);
    __shared__ float ws[8];
    __shared__ float sres;
    if ((t & 31) == 0) ws[t >> 5] = sq;
    __syncthreads();
    if (t < 32) {
        float total = (t < 8) ? ws[t] : 0.0f;
#pragma unroll
        for (int o = 4; o > 0; o >>= 1) total += __shfl_xor_sync(0xffffffffu, total, o);
        if (t == 0) sres = rsqrtf(total + EPS_F);
    }
    __syncthreads();
    float vn = v * sres;

    __nv_bfloat16 h = __float2bfloat16_rn(vn);

    if (row < N_Q) {
        size_t i = (size_t)row * DIM + t;
        g_fxn[i] = vn;
        g_ah[i] = h;
    } else {
        size_t i = (size_t)(row - N_Q) * DIM + t;
        float r1 = vn - __bfloat162float(h);
        g_fyn[i] = vn;
        g_bh[i] = h;
        g_bm[i] = __float2bfloat16_rn(r1);
    }
}

// ---------------------------------------------------------------------------
// Kernel 3: sim_approx = h·h' + h·m'  (= h · round(v'))  via HMMA.
// Error vs exact <= ||m||*||v'|| ~ 5e-4 absolute, covered by SCAN_MARGIN.
// 256x128 CTA tile, 8 warps of 64x64, 4 k-chunks, 2-stage cp.async pipeline.
// Epilogue writes sim + per-row 64-col tile maxes.
// ---------------------------------------------------------------------------
#define SBM 256
#define SBN 128
#define TILE_A (SBM * 128)            // 32 KB (A hi split)
#define TILE_B (SBN * 128)            // 16 KB (one B split)
#define STG    (TILE_A + 2 * TILE_B)  // 64 KB
#define SIM_SMEM (2 * STG)            // 128 KB
#define NCHUNK 4                      // 4 x 64-k chunks

#define SWZ(o) ((o) ^ (((o) >> 3) & 0x70))

__device__ __forceinline__ u32 s2u(const void* p) {
    u32 a; asm("{ .reg .u64 t; cvta.to.shared.u64 t, %1; cvt.u32.u64 %0, t; }"
               : "=r"(a) : "l"(p)); return a;
}
__device__ __forceinline__ void cp16(u32 dst, const void* src) {
    asm volatile("cp.async.cg.shared.global [%0], [%1], 16;"
                 :: "r"(dst), "l"(src) : "memory");
}
__device__ __forceinline__ void ldsm4(u32* r, u32 addr) {
    asm volatile("ldmatrix.sync.aligned.m8n8.x4.shared.b16 {%0,%1,%2,%3}, [%4];"
                 : "=r"(r[0]), "=r"(r[1]), "=r"(r[2]), "=r"(r[3]) : "r"(addr));
}
__device__ __forceinline__ void mma16816(float* c, const u32* a, const u32* b) {
    asm volatile(
        "mma.sync.aligned.m16n8k16.row.col.f32.bf16.bf16.f32 "
        "{%0,%1,%2,%3}, {%4,%5,%6,%7}, {%8,%9}, {%0,%1,%2,%3};"
        : "+f"(c[0]), "+f"(c[1]), "+f"(c[2]), "+f"(c[3])
        : "r"(a[0]), "r"(a[1]), "r"(a[2]), "r"(a[3]), "r"(b[0]), "r"(b[1]));
}

__global__ __launch_bounds__(256, 1)
void sim_mma_kernel()
{
    extern __shared__ char dyn[];
    const u32 sbase = s2u(dyn);
    const int tid  = threadIdx.x;
    const int wid  = tid >> 5;
    const int lane = tid & 31;
    const int wm   = wid >> 1;
    const int wn   = wid & 1;
    const int r0   = blockIdx.y * SBM;
    const int c0   = blockIdx.x * SBN;

    float acc[4][8][4];
#pragma unroll
    for (int i = 0; i < 4; i++)
#pragma unroll
        for (int j = 0; j < 8; j++)
#pragma unroll
            for (int q = 0; q < 4; q++) acc[i][j][q] = 0.0f;

    auto loadStage = [&](int s) {
        const int buf = s & 1;
        const u32 base = sbase + buf * STG;
        const int k0 = s * 64;
        const __nv_bfloat16* gAh = g_ah + (size_t)r0 * DIM + k0;
        const __nv_bfloat16* gBh = g_bh + (size_t)c0 * DIM + k0;
        const __nv_bfloat16* gBm = g_bm + (size_t)c0 * DIM + k0;
#pragma unroll
        for (int i = 0; i < 8; i++) {             // A: 256 rows x 8 chunks
            int id = tid + i * 256;
            int r = id >> 3, kc = id & 7;
            u32 so = SWZ((u32)(r * 128 + kc * 16));
            cp16(base + so, gAh + (size_t)r * DIM + kc * 8);
        }
#pragma unroll
        for (int i = 0; i < 4; i++) {             // B: 128 rows x 8 chunks
            int id = tid + i * 256;
            int r = id >> 3, kc = id & 7;
            u32 so = SWZ((u32)(r * 128 + kc * 16));
            const size_t go = (size_t)r * DIM + kc * 8;
            cp16(base + TILE_A + so,          gBh + go);
            cp16(base + TILE_A + TILE_B + so, gBm + go);
        }
        asm volatile("cp.async.commit_group;" ::: "memory");
    };

    loadStage(0);
    loadStage(1);

    for (int s = 0; s < NCHUNK; s++) {
        if (s < NCHUNK - 1)
            asm volatile("cp.async.wait_group 1;" ::: "memory");
        else
            asm volatile("cp.async.wait_group 0;" ::: "memory");
        __syncthreads();

        const u32 base = sbase + (s & 1) * STG;
        const u32 sAh = base;
        const u32 sBh = base + TILE_A;
        const u32 sBm = base + TILE_A + TILE_B;

#pragma unroll
        for (int ks = 0; ks < 4; ks++) {
            u32 A1[4][4], B1[4][4], B2[4][4];
            const int kbA = ks * 32 + (lane >> 4) * 16;
            const int kbB = ks * 32 + ((lane >> 3) & 1) * 16;
#pragma unroll
            for (int mt = 0; mt < 4; mt++) {
                int mr = wm * 64 + mt * 16 + (lane & 15);
                ldsm4(A1[mt], sAh + SWZ(mr * 128 + kbA));
            }
#pragma unroll
            for (int np = 0; np < 4; np++) {
                int nr = wn * 64 + np * 16 + ((lane >> 4) & 1) * 8 + (lane & 7);
                ldsm4(B1[np], sBh + SWZ(nr * 128 + kbB));
            }
#pragma unroll
            for (int np = 0; np < 4; np++) {
                int nr = wn * 64 + np * 16 + ((lane >> 4) & 1) * 8 + (lane & 7);
                ldsm4(B2[np], sBm + SWZ(nr * 128 + kbB));
            }
#pragma unroll
            for (int mt = 0; mt < 4; mt++)
#pragma unroll
                for (int nt = 0; nt < 8; nt++) {
                    mma16816(acc[mt][nt], A1[mt], &B1[nt >> 1][(nt & 1) * 2]);
                    mma16816(acc[mt][nt], A1[mt], &B2[nt >> 1][(nt & 1) * 2]);
                }
        }

        if (s + 2 < NCHUNK) {
            __syncthreads();
            loadStage(s + 2);
        }
    }

#pragma unroll
    for (int mt = 0; mt < 4; mt++) {
        int rlo = r0 + wm * 64 + mt * 16 + (lane >> 2);
#pragma unroll
        for (int nt = 0; nt < 8; nt++) {
            int col = c0 + wn * 64 + nt * 8 + (lane & 3) * 2;
            float2 v0 = make_float2(acc[mt][nt][0], acc[mt][nt][1]);
            float2 v1 = make_float2(acc[mt][nt][2], acc[mt][nt][3]);
            *(float2*)(g_sim + (size_t)rlo * M_KV + col)       = v0;
            *(float2*)(g_sim + (size_t)(rlo + 8) * M_KV + col) = v1;
        }
    }

    // ---- per-row 64-col tile maxes (warp fragment = 64 rows x 64 cols) ----
    const int tile_id = blockIdx.x * 2 + wn;
#pragma unroll
    for (int mt = 0; mt < 4; mt++) {
        float m0 = -3.0e38f, m1 = -3.0e38f;
#pragma unroll
        for (int nt = 0; nt < 8; nt++) {
            m0 = fmaxf(m0, fmaxf(acc[mt][nt][0], acc[mt][nt][1]));
            m1 = fmaxf(m1, fmaxf(acc[mt][nt][2], acc[mt][nt][3]));
        }
        m0 = fmaxf(m0, __shfl_xor_sync(0xffffffffu, m0, 1));
        m0 = fmaxf(m0, __shfl_xor_sync(0xffffffffu, m0, 2));
        m1 = fmaxf(m1, __shfl_xor_sync(0xffffffffu, m1, 1));
        m1 = fmaxf(m1, __shfl_xor_sync(0xffffffffu, m1, 2));
        if ((lane & 3) == 0) {
            int rlo = r0 + wm * 64 + mt * 16 + (lane >> 2);
            g_rtm[(size_t)rlo * NTILE + tile_id]       = m0;
            g_rtm[(size_t)(rlo + 8) * NTILE + tile_id] = m1;
        }
    }
}

// ---------------------------------------------------------------------------
// top-k helpers
// ---------------------------------------------------------------------------
__device__ __forceinline__ u32 ordf(float f) {
    u32 b = __float_as_uint(f);
    return (b & 0x80000000u) ? ~b : (b | 0x80000000u);
}
__device__ __forceinline__ float key_val(u64 k) {
    u32 o = (u32)(k >> 32);
    u32 b = (o & 0x80000000u) ? (o ^ 0x80000000u) : ~o;
    return __uint_as_float(b);
}
__device__ __forceinline__ u64 make_key(float v, int idx) {
    return ((u64)ordf(v) << 32) | (u32)(~(u32)idx);
}
__device__ __forceinline__ u64 kmax(u64 a, u64 b) { return a > b ? a : b; }
__device__ __forceinline__ u64 kmin(u64 a, u64 b) { return a < b ? a : b; }
__device__ __forceinline__ u64 shflx(u64 v, int m) {
    return __shfl_xor_sync(0xffffffffu, v, m);
}
__device__ __forceinline__ void sort32(u64& c, int lane) {
#pragma unroll
    for (int k = 2; k <= 32; k <<= 1) {
#pragma unroll
        for (int j = k >> 1; j > 0; j >>= 1) {
            u64 o = shflx(c, j);
            bool lower = (lane & j) == 0;
            bool desc  = (lane & k) == 0;
            c = (lower == desc) ? kmax(c, o) : kmin(c, o);
        }
    }
}
__device__ __forceinline__ void bimerge32(u64& L, int lane) {
#pragma unroll
    for (int j = 16; j > 0; j >>= 1) {
        u64 o = shflx(L, j);
        bool lower = (lane & j) == 0;
        L = lower ? kmax(L, o) : kmin(L, o);
    }
}
__device__ __forceinline__ void merge32(u64& L, u64 c, int lane) {
    sort32(c, lane);
    u64 cr = shflx(c, 31);
    L = kmax(L, cr);
    bimerge32(L, lane);
}
__device__ __forceinline__ void merge64(u64& L0, u64& L1, u64 c, int lane) {
    sort32(c, lane);                 // desc
    u64 cr = shflx(c, 31);           // asc
    L1 = kmax(L1, cr);               // top-32 of L1∪c (bitonic)
    bimerge32(L1, lane);             // -> sorted desc
    u64 l1r = shflx(L1, 31);         // asc; (L0 desc | l1r asc) = bitonic-64
    u64 hi = kmax(L0, l1r);
    u64 lo = kmin(L0, l1r);
    bimerge32(hi, lane);
    bimerge32(lo, lane);
    L0 = hi; L1 = lo;
}

// ---------------------------------------------------------------------------
// Kernel 4a: tile-max-guided scan (margin widened for 2-term approx).
// ---------------------------------------------------------------------------
__global__ __launch_bounds__(256)
void topk_scan_kernel()
{
    __shared__ u64 sbuf[8][64];
    const unsigned FULL = 0xffffffffu;
    const int warp = threadIdx.x >> 5;
    const int lane = threadIdx.x & 31;
    const int row  = blockIdx.x * 8 + warp;
    u64* buf = sbuf[warp];
    const float* rp = g_sim + (size_t)row * M_KV;

    float4 rv = *(const float4*)(g_rtm + (size_t)row * NTILE + lane * 4);
    float rtmreg[4] = {rv.x, rv.y, rv.z, rv.w};

    const u64 SENTK = (u64)ordf(-3.0e38f) << 32;
    u64 TL = SENTK;
#pragma unroll
    for (int j = 0; j < 4; j++) {
        u64 c = (u64)ordf(rtmreg[j]) << 32;
        merge32(TL, c, lane);
    }
    const float v0 = key_val(__shfl_sync(FULL, TL, 31)) - SCAN_MARGIN;

    u64 L0 = SENTK, L1 = SENTK;
    float mn = v0;
    int cnt = 0;

    for (int tb = 0; tb < 32; tb++) {
#pragma unroll
        for (int j = 0; j < 4; j++) {
            float rtm = __shfl_sync(FULL, rtmreg[j], tb);
            if (rtm < mn) continue;                 // warp-uniform skip
            const int t = tb * 4 + j;
            float2 e = *(const float2*)(rp + t * 64 + lane * 2);
#pragma unroll
            for (int q = 0; q < 2; q++) {
                float cv = q ? e.y : e.x;
                unsigned bal = __ballot_sync(FULL, cv >= mn);
                if (bal) {
                    bool mine = (cv >= mn);
                    int pos = cnt + __popc(bal & ((1u << lane) - 1));
                    if (mine) buf[pos] = make_key(cv, t * 64 + lane * 2 + q);
                    cnt += __popc(bal);
                    while (cnt >= 32) {
                        __syncwarp();
                        u64 cd = buf[lane];
                        if (lane < cnt - 32) buf[lane] = buf[32 + lane];
                        __syncwarp();
                        cnt -= 32;
                        merge64(L0, L1, cd, lane);
                        mn = fmaxf(v0, key_val(__shfl_sync(FULL, L1, 31)));
                    }
                }
            }
        }
    }
    if (cnt > 0) {
        __syncwarp();
        u64 cd = (lane < cnt) ? buf[lane] : 0ull;
        merge64(L0, L1, cd, lane);
    }

    g_cand[(size_t)row * 64 + lane]      = (int)(~(u32)L0);
    g_cand[(size_t)row * 64 + lane + 32] = (int)(~(u32)L1);
}

// ---------------------------------------------------------------------------
// Kernel 4b: sequential-fp32 re-rank (unchanged, bit-identical arithmetic).
// ---------------------------------------------------------------------------
#define TK_WARPS 4

__global__ __launch_bounds__(128)
void topk_rerank_kernel(float* __restrict__ out, int out_size)
{
    __shared__ int   scid[TK_WARPS][64];
    __shared__ float ssfx[TK_WARPS][256];
    __shared__ float stile[TK_WARPS][32][65];
    const unsigned FULL = 0xffffffffu;
    const int warp = threadIdx.x >> 5;
    const int lane = threadIdx.x & 31;
    const int row  = blockIdx.x * TK_WARPS + warp;
    int* cid = scid[warp];
    float* sfx = ssfx[warp];

    int c0i = g_cand[(size_t)row * 64 + lane];
    int c1i = g_cand[(size_t)row * 64 + lane + 32];
    const bool ok0 = ((u32)c0i < (u32)M_KV);
    const bool ok1 = ((u32)c1i < (u32)M_KV);
    cid[lane]      = ok0 ? c0i : 0;
    cid[lane + 32] = ok1 ? c1i : 0;
    {
        float4 a = *(const float4*)(g_fxn + (size_t)row * DIM + lane * 8);
        float4 b = *(const float4*)(g_fxn + (size_t)row * DIM + lane * 8 + 4);
        *(float4*)(sfx + lane * 8)     = a;
        *(float4*)(sfx + lane * 8 + 4) = b;
    }
    __syncwarp();

    float p0 = 0.0f, p1 = 0.0f;
    for (int c8 = 0; c8 < 8; c8++) {
        const int k0 = c8 * 32;
#pragma unroll
        for (int it = 0; it < 16; it++) {
            int r  = it * 4 + (lane >> 3);
            int f4 = lane & 7;
            float4 v = *(const float4*)(g_fyn + (size_t)cid[r] * DIM + k0 + f4 * 4);
            stile[warp][f4 * 4 + 0][r] = v.x;
            stile[warp][f4 * 4 + 1][r] = v.y;
            stile[warp][f4 * 4 + 2][r] = v.z;
            stile[warp][f4 * 4 + 3][r] = v.w;
        }
        __syncwarp();
#pragma unroll
        for (int kk = 0; kk < 32; kk++) {
            float a = sfx[k0 + kk];
            p0 = fmaf(a, stile[warp][kk][lane],      p0);
            p1 = fmaf(a, stile[warp][kk][lane + 32], p1);
        }
        __syncwarp();
    }
    u64 ex0 = ok0 ? make_key(p0, c0i) : 0ull;
    u64 ex1 = ok1 ? make_key(p1, c1i) : 0ull;

    sort32(ex0, lane);
    sort32(ex1, lane);
    u64 r1 = shflx(ex1, 31);
    ex0 = kmax(ex0, r1);
    bimerge32(ex0, lane);

    float v   = key_val(ex0);
    int   idx = (int)(~(u32)ex0);
    float top = __shfl_sync(FULL, v, 0);
    float e = expf((v - top) / TAU_F);
    float s = e;
#pragma unroll
    for (int o = 16; o > 0; o >>= 1) s += __shfl_xor_sync(FULL, s, o);
    float soft = e / s;

    out[(size_t)row * KNB + lane] = soft;
    if (out_size >= 2 * N_Q * KNB)
        out[(size_t)N_Q * KNB + (size_t)row * KNB + lane] = (float)idx;
}

// ---------------------------------------------------------------------------
extern "C" void kernel_launch(void* const* d_in, const int* in_sizes, int n_in,
                              void* d_out, int out_size)
{
    const float* x = (const float*)d_in[0];
    const float* y = (const float*)d_in[1];
    const float* W = (const float*)d_in[2];
    const float* b = (const float*)d_in[3];
    float* out = (float*)d_out;
    (void)in_sizes; (void)n_in;

    cudaFuncSetAttribute(sim_mma_kernel,
                         cudaFuncAttributeMaxDynamicSharedMemorySize, SIM_SMEM);

    feat_gemm_kernel<<<dim3(DIM / FBN, (N_Q + M_KV) / FBM), 256>>>(x, y, W, b);
    normalize_split_kernel<<<N_Q + M_KV, 256>>>();
    sim_mma_kernel<<<dim3(M_KV / SBN, N_Q / SBM), 256, SIM_SMEM>>>();
    topk_scan_kernel<<<N_Q / 8, 256>>>();
    topk_rerank_kernel<<<N_Q / TK_WARPS, 128>>>(out, out_size);
}

// round 17
// speedup vs baseline: 2.2110x; 1.0472x over previous
#include <cuda_runtime.h>
#include <cuda_bf16.h>
#include <cuda_fp16.h>
#include <math.h>
#include <stdint.h>

#define N_Q   8192
#define M_KV  8192
#define DIM   256
#define KNB   32
#define TAU_F 0.07f
#define EPS_F 1e-8f

#define NTILE 128    // 64-col tiles per row
#define SCAN_MARGIN 3e-3f   // 2-term approx (5e-4) + fp16 store (5e-4), 3x headroom

// ---------------- scratch (device globals; allocation-free) ----------------
__device__ float g_F[16384 * 256];                          // 16 MB features pre-norm
__device__ float g_fxn[(size_t)N_Q * DIM];                  // 8 MB fp32 normalized x
__device__ float g_fyn[(size_t)M_KV * DIM];                 // 8 MB fp32 normalized y
__device__ __nv_bfloat16 g_ah[(size_t)N_Q * DIM];           // 4 MB x split hi
__device__ __nv_bfloat16 g_bh[(size_t)M_KV * DIM];          // 4 MB y split hi
__device__ __nv_bfloat16 g_bm[(size_t)M_KV * DIM];          // 4 MB y split mid
__device__ __half g_simh[(size_t)N_Q * M_KV];               // 128 MB approx similarity (fp16)
__device__ float g_rtm[(size_t)N_Q * NTILE];                // 4 MB per-row 64-col tile maxes
__device__ int   g_cand[(size_t)N_Q * 64];                  // 2 MB top-64 candidate ids (-1 = none)

typedef unsigned long long u64;
typedef unsigned int u32;

// ---------------- f32x2 helpers (feat GEMM) ----------------
__device__ __forceinline__ u64 pk2(float lo, float hi) {
    u64 r; asm("mov.b64 %0, {%1, %2};" : "=l"(r) : "f"(lo), "f"(hi)); return r;
}
__device__ __forceinline__ void unpk2(u64 p, float& lo, float& hi) {
    asm("mov.b64 {%0, %1}, %2;" : "=f"(lo), "=f"(hi) : "l"(p));
}
__device__ __forceinline__ void ffma2(u64& d, u64 a, u64 b) {
    asm("fma.rn.f32x2 %0, %1, %2, %0;" : "+l"(d) : "l"(a), "l"(b));
}

// ---------------------------------------------------------------------------
// Kernel 1: F = [x;y] @ W^T + b   (fp32 exact; R1 body — best measured)
// ---------------------------------------------------------------------------
#define FBM 128
#define FBN 128
#define FBK 16
#define FSST 132

__global__ __launch_bounds__(256, 2)
void feat_gemm_kernel(const float* __restrict__ x, const float* __restrict__ y,
                      const float* __restrict__ W, const float* __restrict__ bias)
{
    __shared__ float As[FBK * FSST];
    __shared__ float Bs[FBK * FSST];
    const int tid = threadIdx.x;
    const int tr  = tid >> 4;
    const int tc  = tid & 15;
    const int r0  = blockIdx.y * FBM;
    const int c0  = blockIdx.x * FBN;

    u64 acc[8][4];
#pragma unroll
    for (int i = 0; i < 8; i++)
#pragma unroll
        for (int j = 0; j < 4; j++) acc[i][j] = 0ull;

    for (int k0 = 0; k0 < DIM; k0 += FBK) {
#pragma unroll
        for (int ld = 0; ld < 2; ld++) {
            int pos = tid + ld * 256;
            int r   = pos >> 2;
            int kg  = pos & 3;
            int gr  = r0 + r;
            const float* src = (gr < N_Q) ? (x + (size_t)gr * DIM)
                                          : (y + (size_t)(gr - N_Q) * DIM);
            float4 v = *(const float4*)(src + k0 + kg * 4);
            As[(kg * 4 + 0) * FSST + r] = v.x;
            As[(kg * 4 + 1) * FSST + r] = v.y;
            As[(kg * 4 + 2) * FSST + r] = v.z;
            As[(kg * 4 + 3) * FSST + r] = v.w;
        }
#pragma unroll
        for (int ld = 0; ld < 2; ld++) {
            int pos = tid + ld * 256;
            int c   = pos >> 2;
            int kg  = pos & 3;
            float4 v = *(const float4*)(W + (size_t)(c0 + c) * DIM + k0 + kg * 4);
            Bs[(kg * 4 + 0) * FSST + c] = v.x;
            Bs[(kg * 4 + 1) * FSST + c] = v.y;
            Bs[(kg * 4 + 2) * FSST + c] = v.z;
            Bs[(kg * 4 + 3) * FSST + c] = v.w;
        }
        __syncthreads();
#pragma unroll
        for (int kk = 0; kk < FBK; kk++) {
            const float* ar = As + kk * FSST + tr * 8;
            const u64*   br = (const u64*)(Bs + kk * FSST + tc * 8);
            float4 a0 = *(const float4*)(ar);
            float4 a1 = *(const float4*)(ar + 4);
            u64 b0 = br[0], b1 = br[1], b2 = br[2], b3 = br[3];
            float av[8] = {a0.x, a0.y, a0.z, a0.w, a1.x, a1.y, a1.z, a1.w};
#pragma unroll
            for (int i = 0; i < 8; i++) {
                u64 ai = pk2(av[i], av[i]);
                ffma2(acc[i][0], ai, b0);
                ffma2(acc[i][1], ai, b1);
                ffma2(acc[i][2], ai, b2);
                ffma2(acc[i][3], ai, b3);
            }
        }
        __syncthreads();
    }

    float bl[8];
#pragma unroll
    for (int u = 0; u < 8; u++) bl[u] = bias[c0 + tc * 8 + u];
#pragma unroll
    for (int i = 0; i < 8; i++) {
        int row = r0 + tr * 8 + i;
        float* dst = g_F + (size_t)row * DIM + c0 + tc * 8;
        float4 w0, w1;
        unpk2(acc[i][0], w0.x, w0.y); unpk2(acc[i][1], w0.z, w0.w);
        unpk2(acc[i][2], w1.x, w1.y); unpk2(acc[i][3], w1.z, w1.w);
        w0.x += bl[0]; w0.y += bl[1]; w0.z += bl[2]; w0.w += bl[3];
        w1.x += bl[4]; w1.y += bl[5]; w1.z += bl[6]; w1.w += bl[7];
        *(float4*)dst       = w0;
        *(float4*)(dst + 4) = w1;
    }
}

// ---------------------------------------------------------------------------
// Kernel 2: L2-normalize rows of F (2 rows per 512-thread block; per-row
// reduction structure identical to the single-row version — bit-exact).
// ---------------------------------------------------------------------------
__global__ __launch_bounds__(512)
void normalize_split_kernel()
{
    const int sub = threadIdx.x >> 8;        // 0 or 1: which row in this block
    const int t   = threadIdx.x & 255;
    const int row = blockIdx.x * 2 + sub;
    float v = g_F[(size_t)row * DIM + t];
    float sq = v * v;
#pragma unroll
    for (int o = 16; o > 0; o >>= 1) sq += __shfl_xor_sync(0xffffffffu, sq, o);
    __shared__ float ws[2][8];
    __shared__ float sres[2];
    if ((t & 31) == 0) ws[sub][t >> 5] = sq;
    __syncthreads();
    if (t < 32) {
        float total = (t < 8) ? ws[sub][t] : 0.0f;
#pragma unroll
        for (int o = 4; o > 0; o >>= 1) total += __shfl_xor_sync(0xffffffffu, total, o);
        if (t == 0) sres[sub] = rsqrtf(total + EPS_F);
    }
    __syncthreads();
    float vn = v * sres[sub];

    __nv_bfloat16 h = __float2bfloat16_rn(vn);

    if (row < N_Q) {
        size_t i = (size_t)row * DIM + t;
        g_fxn[i] = vn;
        g_ah[i] = h;
    } else {
        size_t i = (size_t)(row - N_Q) * DIM + t;
        float r1 = vn - __bfloat162float(h);
        g_fyn[i] = vn;
        g_bh[i] = h;
        g_bm[i] = __float2bfloat16_rn(r1);
    }
}

// ---------------------------------------------------------------------------
// Kernel 3: sim_approx = h·h' + h·m' via HMMA; fp16 store + fp32 tile maxes.
// ---------------------------------------------------------------------------
#define SBM 256
#define SBN 128
#define TILE_A (SBM * 128)            // 32 KB (A hi split)
#define TILE_B (SBN * 128)            // 16 KB (one B split)
#define STG    (TILE_A + 2 * TILE_B)  // 64 KB
#define SIM_SMEM (2 * STG)            // 128 KB
#define NCHUNK 4

#define SWZ(o) ((o) ^ (((o) >> 3) & 0x70))

__device__ __forceinline__ u32 s2u(const void* p) {
    u32 a; asm("{ .reg .u64 t; cvta.to.shared.u64 t, %1; cvt.u32.u64 %0, t; }"
               : "=r"(a) : "l"(p)); return a;
}
__device__ __forceinline__ void cp16(u32 dst, const void* src) {
    asm volatile("cp.async.cg.shared.global [%0], [%1], 16;"
                 :: "r"(dst), "l"(src) : "memory");
}
__device__ __forceinline__ void ldsm4(u32* r, u32 addr) {
    asm volatile("ldmatrix.sync.aligned.m8n8.x4.shared.b16 {%0,%1,%2,%3}, [%4];"
                 : "=r"(r[0]), "=r"(r[1]), "=r"(r[2]), "=r"(r[3]) : "r"(addr));
}
__device__ __forceinline__ void mma16816(float* c, const u32* a, const u32* b) {
    asm volatile(
        "mma.sync.aligned.m16n8k16.row.col.f32.bf16.bf16.f32 "
        "{%0,%1,%2,%3}, {%4,%5,%6,%7}, {%8,%9}, {%0,%1,%2,%3};"
        : "+f"(c[0]), "+f"(c[1]), "+f"(c[2]), "+f"(c[3])
        : "r"(a[0]), "r"(a[1]), "r"(a[2]), "r"(a[3]), "r"(b[0]), "r"(b[1]));
}

__global__ __launch_bounds__(256, 1)
void sim_mma_kernel()
{
    extern __shared__ char dyn[];
    const u32 sbase = s2u(dyn);
    const int tid  = threadIdx.x;
    const int wid  = tid >> 5;
    const int lane = tid & 31;
    const int wm   = wid >> 1;
    const int wn   = wid & 1;
    const int r0   = blockIdx.y * SBM;
    const int c0   = blockIdx.x * SBN;

    float acc[4][8][4];
#pragma unroll
    for (int i = 0; i < 4; i++)
#pragma unroll
        for (int j = 0; j < 8; j++)
#pragma unroll
            for (int q = 0; q < 4; q++) acc[i][j][q] = 0.0f;

    auto loadStage = [&](int s) {
        const int buf = s & 1;
        const u32 base = sbase + buf * STG;
        const int k0 = s * 64;
        const __nv_bfloat16* gAh = g_ah + (size_t)r0 * DIM + k0;
        const __nv_bfloat16* gBh = g_bh + (size_t)c0 * DIM + k0;
        const __nv_bfloat16* gBm = g_bm + (size_t)c0 * DIM + k0;
#pragma unroll
        for (int i = 0; i < 8; i++) {
            int id = tid + i * 256;
            int r = id >> 3, kc = id & 7;
            u32 so = SWZ((u32)(r * 128 + kc * 16));
            cp16(base + so, gAh + (size_t)r * DIM + kc * 8);
        }
#pragma unroll
        for (int i = 0; i < 4; i++) {
            int id = tid + i * 256;
            int r = id >> 3, kc = id & 7;
            u32 so = SWZ((u32)(r * 128 + kc * 16));
            const size_t go = (size_t)r * DIM + kc * 8;
            cp16(base + TILE_A + so,          gBh + go);
            cp16(base + TILE_A + TILE_B + so, gBm + go);
        }
        asm volatile("cp.async.commit_group;" ::: "memory");
    };

    loadStage(0);
    loadStage(1);

    for (int s = 0; s < NCHUNK; s++) {
        if (s < NCHUNK - 1)
            asm volatile("cp.async.wait_group 1;" ::: "memory");
        else
            asm volatile("cp.async.wait_group 0;" ::: "memory");
        __syncthreads();

        const u32 base = sbase + (s & 1) * STG;
        const u32 sAh = base;
        const u32 sBh = base + TILE_A;
        const u32 sBm = base + TILE_A + TILE_B;

#pragma unroll
        for (int ks = 0; ks < 4; ks++) {
            u32 A1[4][4], B1[4][4], B2[4][4];
            const int kbA = ks * 32 + (lane >> 4) * 16;
            const int kbB = ks * 32 + ((lane >> 3) & 1) * 16;
#pragma unroll
            for (int mt = 0; mt < 4; mt++) {
                int mr = wm * 64 + mt * 16 + (lane & 15);
                ldsm4(A1[mt], sAh + SWZ(mr * 128 + kbA));
            }
#pragma unroll
            for (int np = 0; np < 4; np++) {
                int nr = wn * 64 + np * 16 + ((lane >> 4) & 1) * 8 + (lane & 7);
                ldsm4(B1[np], sBh + SWZ(nr * 128 + kbB));
            }
#pragma unroll
            for (int np = 0; np < 4; np++) {
                int nr = wn * 64 + np * 16 + ((lane >> 4) & 1) * 8 + (lane & 7);
                ldsm4(B2[np], sBm + SWZ(nr * 128 + kbB));
            }
#pragma unroll
            for (int mt = 0; mt < 4; mt++)
#pragma unroll
                for (int nt = 0; nt < 8; nt++) {
                    mma16816(acc[mt][nt], A1[mt], &B1[nt >> 1][(nt & 1) * 2]);
                    mma16816(acc[mt][nt], A1[mt], &B2[nt >> 1][(nt & 1) * 2]);
                }
        }

        if (s + 2 < NCHUNK) {
            __syncthreads();
            loadStage(s + 2);
        }
    }

#pragma unroll
    for (int mt = 0; mt < 4; mt++) {
        int rlo = r0 + wm * 64 + mt * 16 + (lane >> 2);
#pragma unroll
        for (int nt = 0; nt < 8; nt++) {
            int col = c0 + wn * 64 + nt * 8 + (lane & 3) * 2;
            __half2 h0 = __floats2half2_rn(acc[mt][nt][0], acc[mt][nt][1]);
            __half2 h1 = __floats2half2_rn(acc[mt][nt][2], acc[mt][nt][3]);
            *(__half2*)(g_simh + (size_t)rlo * M_KV + col)       = h0;
            *(__half2*)(g_simh + (size_t)(rlo + 8) * M_KV + col) = h1;
        }
    }

    // ---- per-row 64-col tile maxes (fp32, pre-rounding) ----
    const int tile_id = blockIdx.x * 2 + wn;
#pragma unroll
    for (int mt = 0; mt < 4; mt++) {
        float m0 = -3.0e38f, m1 = -3.0e38f;
#pragma unroll
        for (int nt = 0; nt < 8; nt++) {
            m0 = fmaxf(m0, fmaxf(acc[mt][nt][0], acc[mt][nt][1]));
            m1 = fmaxf(m1, fmaxf(acc[mt][nt][2], acc[mt][nt][3]));
        }
        m0 = fmaxf(m0, __shfl_xor_sync(0xffffffffu, m0, 1));
        m0 = fmaxf(m0, __shfl_xor_sync(0xffffffffu, m0, 2));
        m1 = fmaxf(m1, __shfl_xor_sync(0xffffffffu, m1, 1));
        m1 = fmaxf(m1, __shfl_xor_sync(0xffffffffu, m1, 2));
        if ((lane & 3) == 0) {
            int rlo = r0 + wm * 64 + mt * 16 + (lane >> 2);
            g_rtm[(size_t)rlo * NTILE + tile_id]       = m0;
            g_rtm[(size_t)(rlo + 8) * NTILE + tile_id] = m1;
        }
    }
}

// ---------------------------------------------------------------------------
// top-k helpers
// ---------------------------------------------------------------------------
__device__ __forceinline__ u32 ordf(float f) {
    u32 b = __float_as_uint(f);
    return (b & 0x80000000u) ? ~b : (b | 0x80000000u);
}
__device__ __forceinline__ float key_val(u64 k) {
    u32 o = (u32)(k >> 32);
    u32 b = (o & 0x80000000u) ? (o ^ 0x80000000u) : ~o;
    return __uint_as_float(b);
}
__device__ __forceinline__ u64 make_key(float v, int idx) {
    return ((u64)ordf(v) << 32) | (u32)(~(u32)idx);
}
__device__ __forceinline__ u64 kmax(u64 a, u64 b) { return a > b ? a : b; }
__device__ __forceinline__ u64 kmin(u64 a, u64 b) { return a < b ? a : b; }
__device__ __forceinline__ u64 shflx(u64 v, int m) {
    return __shfl_xor_sync(0xffffffffu, v, m);
}
__device__ __forceinline__ void sort32(u64& c, int lane) {
#pragma unroll
    for (int k = 2; k <= 32; k <<= 1) {
#pragma unroll
        for (int j = k >> 1; j > 0; j >>= 1) {
            u64 o = shflx(c, j);
            bool lower = (lane & j) == 0;
            bool desc  = (lane & k) == 0;
            c = (lower == desc) ? kmax(c, o) : kmin(c, o);
        }
    }
}
__device__ __forceinline__ void bimerge32(u64& L, int lane) {
#pragma unroll
    for (int j = 16; j > 0; j >>= 1) {
        u64 o = shflx(L, j);
        bool lower = (lane & j) == 0;
        L = lower ? kmax(L, o) : kmin(L, o);
    }
}
__device__ __forceinline__ void merge32(u64& L, u64 c, int lane) {
    sort32(c, lane);
    u64 cr = shflx(c, 31);
    L = kmax(L, cr);
    bimerge32(L, lane);
}
__device__ __forceinline__ void merge64(u64& L0, u64& L1, u64 c, int lane) {
    sort32(c, lane);                 // desc
    u64 cr = shflx(c, 31);           // asc
    L1 = kmax(L1, cr);               // top-32 of L1∪c (bitonic)
    bimerge32(L1, lane);             // -> sorted desc
    u64 l1r = shflx(L1, 31);         // asc; (L0 desc | l1r asc) = bitonic-64
    u64 hi = kmax(L0, l1r);
    u64 lo = kmin(L0, l1r);
    bimerge32(hi, lane);
    bimerge32(lo, lane);
    L0 = hi; L1 = lo;
}

// ---------------------------------------------------------------------------
// Kernel 4a: tile-max-guided scan over fp16 sims.
// Compact tile list (rtm >= v0) built up-front; streamed with 1-deep prefetch
// so loads pipeline. Evolving mn still filters insertions (superset safe).
// ---------------------------------------------------------------------------
__global__ __launch_bounds__(256)
void topk_scan_kernel()
{
    __shared__ u64   sbuf[8][64];
    __shared__ short stl[8][132];
    const unsigned FULL = 0xffffffffu;
    const int warp = threadIdx.x >> 5;
    const int lane = threadIdx.x & 31;
    const int row  = blockIdx.x * 8 + warp;
    u64* buf = sbuf[warp];
    short* tl = stl[warp];
    const __half* rp = g_simh + (size_t)row * M_KV;

    float4 rv = *(const float4*)(g_rtm + (size_t)row * NTILE + lane * 4);
    float rtmreg[4] = {rv.x, rv.y, rv.z, rv.w};

    const u64 SENTK = (u64)ordf(-3.0e38f) << 32;
    u64 TL = SENTK;
#pragma unroll
    for (int j = 0; j < 4; j++) {
        u64 c = (u64)ordf(rtmreg[j]) << 32;
        merge32(TL, c, lane);
    }
    const float v0 = key_val(__shfl_sync(FULL, TL, 31)) - SCAN_MARGIN;

    // compact list of tiles with rtm >= v0 (>= 32 guaranteed)
    int nl = 0;
#pragma unroll
    for (int j = 0; j < 4; j++) {
        bool p = (rtmreg[j] >= v0);
        unsigned bal = __ballot_sync(FULL, p);
        int pos = nl + __popc(bal & ((1u << lane) - 1));
        if (p) tl[pos] = (short)(lane * 4 + j);
        nl += __popc(bal);
    }
    __syncwarp();

    u64 L0 = SENTK, L1 = SENTK;
    float mn = v0;
    int cnt = 0;

    int t_cur = tl[0];
    __half2 cur = *(const __half2*)(rp + t_cur * 64 + lane * 2);
    for (int i = 0; i < nl; i++) {
        const int t_nxt = (i + 1 < nl) ? tl[i + 1] : t_cur;
        __half2 nxt = *(const __half2*)(rp + t_nxt * 64 + lane * 2);   // prefetch
        float c0 = __low2float(cur);
        float c1 = __high2float(cur);
        const int t = t_cur;
#pragma unroll
        for (int q = 0; q < 2; q++) {
            float cv = q ? c1 : c0;
            unsigned bal = __ballot_sync(FULL, cv >= mn);
            if (bal) {
                bool mine = (cv >= mn);
                int pos = cnt + __popc(bal & ((1u << lane) - 1));
                if (mine) buf[pos] = make_key(cv, t * 64 + lane * 2 + q);
                cnt += __popc(bal);
                while (cnt >= 32) {
                    __syncwarp();
                    u64 cd = buf[lane];
                    if (lane < cnt - 32) buf[lane] = buf[32 + lane];
                    __syncwarp();
                    cnt -= 32;
                    merge64(L0, L1, cd, lane);
                    mn = fmaxf(v0, key_val(__shfl_sync(FULL, L1, 31)));
                }
            }
        }
        t_cur = t_nxt;
        cur = nxt;
    }
    if (cnt > 0) {
        __syncwarp();
        u64 cd = (lane < cnt) ? buf[lane] : 0ull;
        merge64(L0, L1, cd, lane);
    }

    g_cand[(size_t)row * 64 + lane]      = (int)(~(u32)L0);
    g_cand[(size_t)row * 64 + lane + 32] = (int)(~(u32)L1);
}

// ---------------------------------------------------------------------------
// Kernel 4b: sequential-fp32 re-rank (unchanged, bit-identical arithmetic).
// ---------------------------------------------------------------------------
#define TK_WARPS 4

__global__ __launch_bounds__(128)
void topk_rerank_kernel(float* __restrict__ out, int out_size)
{
    __shared__ int   scid[TK_WARPS][64];
    __shared__ float ssfx[TK_WARPS][256];
    __shared__ float stile[TK_WARPS][32][65];
    const unsigned FULL = 0xffffffffu;
    const int warp = threadIdx.x >> 5;
    const int lane = threadIdx.x & 31;
    const int row  = blockIdx.x * TK_WARPS + warp;
    int* cid = scid[warp];
    float* sfx = ssfx[warp];

    int c0i = g_cand[(size_t)row * 64 + lane];
    int c1i = g_cand[(size_t)row * 64 + lane + 32];
    const bool ok0 = ((u32)c0i < (u32)M_KV);
    const bool ok1 = ((u32)c1i < (u32)M_KV);
    cid[lane]      = ok0 ? c0i : 0;
    cid[lane + 32] = ok1 ? c1i : 0;
    {
        float4 a = *(const float4*)(g_fxn + (size_t)row * DIM + lane * 8);
        float4 b = *(const float4*)(g_fxn + (size_t)row * DIM + lane * 8 + 4);
        *(float4*)(sfx + lane * 8)     = a;
        *(float4*)(sfx + lane * 8 + 4) = b;
    }
    __syncwarp();

    float p0 = 0.0f, p1 = 0.0f;
    for (int c8 = 0; c8 < 8; c8++) {
        const int k0 = c8 * 32;
#pragma unroll
        for (int it = 0; it < 16; it++) {
            int r  = it * 4 + (lane >> 3);
            int f4 = lane & 7;
            float4 v = *(const float4*)(g_fyn + (size_t)cid[r] * DIM + k0 + f4 * 4);
            stile[warp][f4 * 4 + 0][r] = v.x;
            stile[warp][f4 * 4 + 1][r] = v.y;
            stile[warp][f4 * 4 + 2][r] = v.z;
            stile[warp][f4 * 4 + 3][r] = v.w;
        }
        __syncwarp();
#pragma unroll
        for (int kk = 0; kk < 32; kk++) {
            float a = sfx[k0 + kk];
            p0 = fmaf(a, stile[warp][kk][lane],      p0);
            p1 = fmaf(a, stile[warp][kk][lane + 32], p1);
        }
        __syncwarp();
    }
    u64 ex0 = ok0 ? make_key(p0, c0i) : 0ull;
    u64 ex1 = ok1 ? make_key(p1, c1i) : 0ull;

    sort32(ex0, lane);
    sort32(ex1, lane);
    u64 r1 = shflx(ex1, 31);
    ex0 = kmax(ex0, r1);
    bimerge32(ex0, lane);

    float v   = key_val(ex0);
    int   idx = (int)(~(u32)ex0);
    float top = __shfl_sync(FULL, v, 0);
    float e = expf((v - top) / TAU_F);
    float s = e;
#pragma unroll
    for (int o = 16; o > 0; o >>= 1) s += __shfl_xor_sync(FULL, s, o);
    float soft = e / s;

    out[(size_t)row * KNB + lane] = soft;
    if (out_size >= 2 * N_Q * KNB)
        out[(size_t)N_Q * KNB + (size_t)row * KNB + lane] = (float)idx;
}

// ---------------------------------------------------------------------------
extern "C" void kernel_launch(void* const* d_in, const int* in_sizes, int n_in,
                              void* d_out, int out_size)
{
    const float* x = (const float*)d_in[0];
    const float* y = (const float*)d_in[1];
    const float* W = (const float*)d_in[2];
    const float* b = (const float*)d_in[3];
    float* out = (float*)d_out;
    (void)in_sizes; (void)n_in;

    cudaFuncSetAttribute(sim_mma_kernel,
                         cudaFuncAttributeMaxDynamicSharedMemorySize, SIM_SMEM);

    feat_gemm_kernel<<<dim3(DIM / FBN, (N_Q + M_KV) / FBM), 256>>>(x, y, W, b);
    normalize_split_kernel<<<(N_Q + M_KV) / 2, 512>>>();
    sim_mma_kernel<<<dim3(M_KV / SBN, N_Q / SBM), 256, SIM_SMEM>>>();
    topk_scan_kernel<<<N_Q / 8, 256>>>();
    topk_rerank_kernel<<<N_Q / TK_WARPS, 128>>>(out, out_size);
}